// round 2
// baseline (speedup 1.0000x reference)
#include <cuda_runtime.h>

static constexpr int S_  = 2048;
static constexpr int B_  = 2;
static constexpr int E_  = 1024;
static constexpr int H_  = 16;
static constexpr int DH_ = 64;
static constexpr int MR_ = S_ * B_;   // 4096 rows of the flattened [S*B, E] view

// ---------------- scratch (device globals: no allocations allowed) ----------
__device__ float g_Q[MR_ * E_];
__device__ float g_K[MR_ * E_];
__device__ float g_V[MR_ * E_];
__device__ float g_attn[MR_ * E_];
__device__ float g_m [B_ * H_ * S_];
__device__ float g_il[B_ * H_ * S_];

// XOR swizzle over a [64 rows][16 float4] tile.
__device__ __forceinline__ int sw(int r, int f) { return r * 16 + (f ^ (r & 15)); }

// Load a 64x64 fp32 tile into swizzled float4 smem. Global reads coalesced.
__device__ __forceinline__ void load_tile64(float4* dst, const float* __restrict__ src,
                                            int row0, int rowStride, int colBase, int tid)
{
    #pragma unroll
    for (int idx = tid; idx < 1024; idx += 256) {
        int r = idx >> 4, f = idx & 15;
        dst[sw(r, f)] = *(const float4*)&src[(size_t)(row0 + r) * rowStride + colBase + f * 4];
    }
}

// 64x64x64: acc[r][c] += sum_k A[i][k] * B[j][k]  (contracts COLUMNS: A @ B^T)
__device__ __forceinline__ void tile_gemm(const float4* As4, const float4* Bs4,
                                          int tx, int ty, float acc[4][4])
{
    #pragma unroll
    for (int f = 0; f < 16; f++) {
        float4 a[4], bb[4];
        #pragma unroll
        for (int r = 0; r < 4; r++) a[r] = As4[sw(ty * 4 + r, f)];
        #pragma unroll
        for (int c = 0; c < 4; c++) bb[c] = Bs4[sw(tx * 4 + c, f)];
        #pragma unroll
        for (int r = 0; r < 4; r++)
            #pragma unroll
            for (int c = 0; c < 4; c++) {
                acc[r][c] = fmaf(a[r].x, bb[c].x, acc[r][c]);
                acc[r][c] = fmaf(a[r].y, bb[c].y, acc[r][c]);
                acc[r][c] = fmaf(a[r].z, bb[c].z, acc[r][c]);
                acc[r][c] = fmaf(a[r].w, bb[c].w, acc[r][c]);
            }
    }
}

// 64x64x64: acc[r][c] += sum_j P[i][j] * V[j][d]  (contracts P's col with V's ROW)
// P stored [i][j] swizzled, V stored [j][d] swizzled.
__device__ __forceinline__ void tile_pv(const float4* Ps4, const float4* Vs4,
                                        int tx, int ty, float acc[4][4])
{
    #pragma unroll
    for (int f = 0; f < 16; f++) {
        float4 p[4];
        #pragma unroll
        for (int r = 0; r < 4; r++) p[r] = Ps4[sw(ty * 4 + r, f)];
        #pragma unroll
        for (int comp = 0; comp < 4; comp++) {
            int j = f * 4 + comp;
            float4 v = Vs4[sw(j, tx)];              // V[j][tx*4 .. tx*4+3]
            #pragma unroll
            for (int r = 0; r < 4; r++) {
                float pj = ((const float*)&p[r])[comp];   // P[i][j]
                acc[r][0] = fmaf(pj, v.x, acc[r][0]);
                acc[r][1] = fmaf(pj, v.y, acc[r][1]);
                acc[r][2] = fmaf(pj, v.z, acc[r][2]);
                acc[r][3] = fmaf(pj, v.w, acc[r][3]);
            }
        }
    }
}

// ---------------- C[m,n] = scale * sum_k A[m,k] W[n,k] (+bias[n]) -----------
__global__ __launch_bounds__(256) void sgemm_xwT(
    const float* __restrict__ A, const float* __restrict__ W,
    const float* __restrict__ bias, float* __restrict__ C,
    int M, int N, int K, float scale)
{
    __shared__ float4 As4[1024];
    __shared__ float4 Ws4[1024];
    int tid = threadIdx.x, tx = tid & 15, ty = tid >> 4;
    int m0 = blockIdx.y * 64, n0 = blockIdx.x * 64;
    float acc[4][4] = {};
    for (int k0 = 0; k0 < K; k0 += 64) {
        __syncthreads();
        load_tile64(As4, A, m0, K, k0, tid);
        load_tile64(Ws4, W, n0, K, k0, tid);
        __syncthreads();
        tile_gemm(As4, Ws4, tx, ty, acc);
    }
    #pragma unroll
    for (int r = 0; r < 4; r++) {
        int m = m0 + ty * 4 + r;
        int n = n0 + tx * 4;
        float4 v;
        v.x = acc[r][0] * scale; v.y = acc[r][1] * scale;
        v.z = acc[r][2] * scale; v.w = acc[r][3] * scale;
        if (bias) {
            float4 bv = *(const float4*)&bias[n];
            v.x += bv.x; v.y += bv.y; v.z += bv.z; v.w += bv.w;
        }
        *(float4*)&C[(size_t)m * N + n] = v;
    }
}

// Apply forgetting factor: f = fc*(fb/(tq - tt + fa)) + fd
__device__ __forceinline__ void apply_forget(float acc[4][4], const float* tq, const float* tt,
                                             int tx, int ty, float fav, float fbv,
                                             float fcv, float fdv)
{
    #pragma unroll
    for (int r = 0; r < 4; r++) {
        float tqv = tq[ty * 4 + r];
        #pragma unroll
        for (int c = 0; c < 4; c++) {
            float fct = fcv * (fbv / (tqv - tt[tx * 4 + c] + fav)) + fdv;
            acc[r][c] *= fct;
        }
    }
}

// ---------------- pass 1: softmax stats (row max + sumexp) ------------------
__global__ __launch_bounds__(256) void attn_stats(
    const float* __restrict__ td,
    const float* __restrict__ fa, const float* __restrict__ fb,
    const float* __restrict__ fc, const float* __restrict__ fd)
{
    __shared__ float4 Qs4[1024];
    __shared__ float4 Ks4[1024];
    __shared__ float tq[64], tt[64];
    int q0 = blockIdx.x * 64, h = blockIdx.y, b = blockIdx.z;
    int tid = threadIdx.x, tx = tid & 15, ty = tid >> 4;
    float fav = *fa, fbv = *fb, fcv = *fc, fdv = *fd;

    load_tile64(Qs4, g_Q + (size_t)b * E_, q0, B_ * E_, h * DH_, tid);
    if (tid < 64) tq[tid] = td[b * S_ + q0 + tid];

    float m_r[4], l_r[4];
    #pragma unroll
    for (int r = 0; r < 4; r++) { m_r[r] = -1e30f; l_r[r] = 0.f; }

    for (int t0 = 0; t0 < S_; t0 += 64) {
        __syncthreads();
        load_tile64(Ks4, g_K + (size_t)b * E_, t0, B_ * E_, h * DH_, tid);
        if (tid < 64) tt[tid] = td[b * S_ + t0 + tid];
        __syncthreads();

        float acc[4][4] = {};
        tile_gemm(Qs4, Ks4, tx, ty, acc);
        apply_forget(acc, tq, tt, tx, ty, fav, fbv, fcv, fdv);

        #pragma unroll
        for (int r = 0; r < 4; r++) {
            float mx = fmaxf(fmaxf(acc[r][0], acc[r][1]), fmaxf(acc[r][2], acc[r][3]));
            #pragma unroll
            for (int o = 8; o > 0; o >>= 1)
                mx = fmaxf(mx, __shfl_xor_sync(0xffffffffu, mx, o));
            float mnew = fmaxf(m_r[r], mx);
            float ps = __expf(acc[r][0] - mnew) + __expf(acc[r][1] - mnew)
                     + __expf(acc[r][2] - mnew) + __expf(acc[r][3] - mnew);
            #pragma unroll
            for (int o = 8; o > 0; o >>= 1)
                ps += __shfl_xor_sync(0xffffffffu, ps, o);
            l_r[r] = l_r[r] * __expf(m_r[r] - mnew) + ps;
            m_r[r] = mnew;
        }
    }
    if (tx == 0) {
        #pragma unroll
        for (int r = 0; r < 4; r++) {
            int srow = q0 + ty * 4 + r;
            g_m [((size_t)b * H_ + h) * S_ + srow] = m_r[r];
            g_il[((size_t)b * H_ + h) * S_ + srow] = 1.0f / l_r[r];
        }
    }
}

// ---------------- pass 2: O = softmax(scores) @ V (per head) ----------------
__global__ __launch_bounds__(256) void attn_out(
    const float* __restrict__ td,
    const float* __restrict__ fa, const float* __restrict__ fb,
    const float* __restrict__ fc, const float* __restrict__ fd)
{
    extern __shared__ float4 smem4[];
    float4* Qs4 = smem4;
    float4* Ks4 = smem4 + 1024;
    float4* Vs4 = smem4 + 2048;
    float4* Ps4 = smem4 + 3072;
    float*  tq  = (float*)(smem4 + 4096);
    float*  tt  = tq + 64;

    int q0 = blockIdx.x * 64, h = blockIdx.y, b = blockIdx.z;
    int tid = threadIdx.x, tx = tid & 15, ty = tid >> 4;
    float fav = *fa, fbv = *fb, fcv = *fc, fdv = *fd;

    load_tile64(Qs4, g_Q + (size_t)b * E_, q0, B_ * E_, h * DH_, tid);
    if (tid < 64) tq[tid] = td[b * S_ + q0 + tid];

    float m_r[4], il_r[4];
    #pragma unroll
    for (int r = 0; r < 4; r++) {
        int srow = q0 + ty * 4 + r;
        m_r[r]  = g_m [((size_t)b * H_ + h) * S_ + srow];
        il_r[r] = g_il[((size_t)b * H_ + h) * S_ + srow];
    }

    float o[4][4] = {};
    for (int t0 = 0; t0 < S_; t0 += 64) {
        __syncthreads();
        load_tile64(Ks4, g_K + (size_t)b * E_, t0, B_ * E_, h * DH_, tid);
        load_tile64(Vs4, g_V + (size_t)b * E_, t0, B_ * E_, h * DH_, tid);
        if (tid < 64) tt[tid] = td[b * S_ + t0 + tid];
        __syncthreads();

        float acc[4][4] = {};
        tile_gemm(Qs4, Ks4, tx, ty, acc);
        apply_forget(acc, tq, tt, tx, ty, fav, fbv, fcv, fdv);

        #pragma unroll
        for (int r = 0; r < 4; r++) {
            float4 w;
            w.x = __expf(acc[r][0] - m_r[r]) * il_r[r];
            w.y = __expf(acc[r][1] - m_r[r]) * il_r[r];
            w.z = __expf(acc[r][2] - m_r[r]) * il_r[r];
            w.w = __expf(acc[r][3] - m_r[r]) * il_r[r];
            Ps4[sw(ty * 4 + r, tx)] = w;   // P[i][j] row-major swizzled
        }
        __syncthreads();
        // O[i][d] += P[i][j] * V[j][d]  — contract over j (V's rows)
        tile_pv(Ps4, Vs4, tx, ty, o);
    }

    #pragma unroll
    for (int r = 0; r < 4; r++) {
        int srow = q0 + ty * 4 + r;
        float4 v; v.x = o[r][0]; v.y = o[r][1]; v.z = o[r][2]; v.w = o[r][3];
        *(float4*)&g_attn[((size_t)srow * B_ + b) * E_ + h * DH_ + tx * 4] = v;
    }
}

// ---------------- pass 3: avg_w[b,s,t] = (1/H) sum_h w -----------------------
__global__ __launch_bounds__(256) void attn_avg(
    const float* __restrict__ td,
    const float* __restrict__ fa, const float* __restrict__ fb,
    const float* __restrict__ fc, const float* __restrict__ fd,
    float* __restrict__ avgw)
{
    __shared__ float4 Qs4[1024];
    __shared__ float4 Ks4[1024];
    __shared__ float tq[64], tt[64];
    int t0 = blockIdx.x * 64, q0 = blockIdx.y * 64, b = blockIdx.z;
    int tid = threadIdx.x, tx = tid & 15, ty = tid >> 4;
    float fav = *fa, fbv = *fb, fcv = *fc, fdv = *fd;

    if (tid < 64)       tq[tid]      = td[b * S_ + q0 + tid];
    else if (tid < 128) tt[tid - 64] = td[b * S_ + t0 + tid - 64];

    float aacc[4][4] = {};
    for (int h = 0; h < H_; h++) {
        __syncthreads();
        load_tile64(Qs4, g_Q + (size_t)b * E_, q0, B_ * E_, h * DH_, tid);
        load_tile64(Ks4, g_K + (size_t)b * E_, t0, B_ * E_, h * DH_, tid);
        __syncthreads();

        float m_r[4], il_r[4];
        #pragma unroll
        for (int r = 0; r < 4; r++) {
            int srow = q0 + ty * 4 + r;
            m_r[r]  = g_m [((size_t)b * H_ + h) * S_ + srow];
            il_r[r] = g_il[((size_t)b * H_ + h) * S_ + srow];
        }

        float acc[4][4] = {};
        tile_gemm(Qs4, Ks4, tx, ty, acc);
        apply_forget(acc, tq, tt, tx, ty, fav, fbv, fcv, fdv);

        #pragma unroll
        for (int r = 0; r < 4; r++) {
            aacc[r][0] += __expf(acc[r][0] - m_r[r]) * il_r[r];
            aacc[r][1] += __expf(acc[r][1] - m_r[r]) * il_r[r];
            aacc[r][2] += __expf(acc[r][2] - m_r[r]) * il_r[r];
            aacc[r][3] += __expf(acc[r][3] - m_r[r]) * il_r[r];
        }
    }
    const float invH = 1.0f / (float)H_;
    #pragma unroll
    for (int r = 0; r < 4; r++) {
        int srow = q0 + ty * 4 + r;
        float4 v;
        v.x = aacc[r][0] * invH; v.y = aacc[r][1] * invH;
        v.z = aacc[r][2] * invH; v.w = aacc[r][3] * invH;
        *(float4*)&avgw[((size_t)b * S_ + srow) * S_ + t0 + tx * 4] = v;
    }
}

// ---------------------------------------------------------------------------
extern "C" void kernel_launch(void* const* d_in, const int* in_sizes, int n_in,
                              void* d_out, int out_size)
{
    const float* query = (const float*)d_in[0];
    const float* key_t = (const float*)d_in[1];
    const float* value = (const float*)d_in[2];
    const float* td    = (const float*)d_in[3];
    const float* q_w   = (const float*)d_in[4];
    const float* k_w   = (const float*)d_in[5];
    const float* v_w   = (const float*)d_in[6];
    const float* out_w = (const float*)d_in[7];
    const float* out_b = (const float*)d_in[8];
    const float* fa    = (const float*)d_in[9];
    const float* fb    = (const float*)d_in[10];
    const float* fc    = (const float*)d_in[11];
    const float* fd    = (const float*)d_in[12];

    float* Z    = (float*)d_out;                        // [S,B,E]
    float* avgw = (float*)d_out + (size_t)S_ * B_ * E_; // [B,S,S]

    float *gQ, *gK, *gV, *gA;
    cudaGetSymbolAddress((void**)&gQ, g_Q);
    cudaGetSymbolAddress((void**)&gK, g_K);
    cudaGetSymbolAddress((void**)&gV, g_V);
    cudaGetSymbolAddress((void**)&gA, g_attn);

    const int smem_out = 4096 * 16 + 2 * 64 * 4;  // 4 tiles + time rows = 66048 B
    cudaFuncSetAttribute(attn_out, cudaFuncAttributeMaxDynamicSharedMemorySize, smem_out);

    dim3 gemm_grid(E_ / 64, MR_ / 64);   // (16, 64)
    // projections
    sgemm_xwT<<<gemm_grid, 256>>>(query, q_w, nullptr, gQ, MR_, E_, E_, 0.125f); // dh^-0.5
    sgemm_xwT<<<gemm_grid, 256>>>(key_t, k_w, nullptr, gK, MR_, E_, E_, 1.0f);
    sgemm_xwT<<<gemm_grid, 256>>>(value, v_w, nullptr, gV, MR_, E_, E_, 1.0f);
    // attention
    attn_stats<<<dim3(S_ / 64, H_, B_), 256>>>(td, fa, fb, fc, fd);
    attn_out<<<dim3(S_ / 64, H_, B_), 256, smem_out>>>(td, fa, fb, fc, fd);
    // output projection
    sgemm_xwT<<<gemm_grid, 256>>>(gA, out_w, out_b, Z, MR_, E_, E_, 1.0f);
    // head-averaged weights
    attn_avg<<<dim3(S_ / 64, S_ / 64, B_), 256>>>(td, fa, fb, fc, fd, avgw);
}

// round 3
// speedup vs baseline: 2.2548x; 2.2548x over previous
#include <cuda_runtime.h>

static constexpr int S_  = 2048;
static constexpr int B_  = 2;
static constexpr int E_  = 1024;
static constexpr int H_  = 16;
static constexpr int DH_ = 64;
static constexpr int MR_ = S_ * B_;   // 4096

// ---------------- scratch (device globals: no allocations allowed) ----------
__device__ float g_Q[MR_ * E_];
__device__ float g_K[MR_ * E_];
__device__ float g_V[MR_ * E_];
__device__ float g_attn[MR_ * E_];
__device__ float g_m [B_ * H_ * S_];
__device__ float g_il[B_ * H_ * S_];

// XOR swizzle over [rows][16 float4]: conflict-free for both broadcast and
// per-lane-distinct float4 access patterns.
__device__ __forceinline__ int sw(int r, int f) { return r * 16 + (f ^ (r & 15)); }

template<int ROWS>
__device__ __forceinline__ void load_tile(float4* dst, const float* __restrict__ src,
                                          int row0, int rowStride, int colBase, int tid)
{
    #pragma unroll
    for (int idx = tid; idx < ROWS * 16; idx += 256) {
        int r = idx >> 4, f = idx & 15;
        dst[sw(r, f)] = *(const float4*)&src[(size_t)(row0 + r) * rowStride + colBase + f * 4];
    }
}

// ======================= 128x128x(K) SGEMM: C = scale*(A @ W^T) + bias ======
// A:[M,K] row-major, W:[N,K] row-major. 256 threads, 8x8 micro, k-tile 16.
__device__ __forceinline__ void gemm_body(const float* __restrict__ A,
                                          const float* __restrict__ W,
                                          const float* __restrict__ bias,
                                          float* __restrict__ C, float scale)
{
    __shared__ float As[16][132];
    __shared__ float Ws[16][132];
    const int K = E_, N = E_;
    int tid = threadIdx.x, tx = tid & 15, ty = tid >> 4;
    int m0 = blockIdx.y * 128, n0 = blockIdx.x * 128;
    int lm = tid >> 1, lk = (tid & 1) * 8;

    float acc[8][8] = {};
    for (int k0 = 0; k0 < K; k0 += 16) {
        // prefetch into registers (overlaps previous compute)
        float4 a0 = *(const float4*)&A[(size_t)(m0 + lm) * K + k0 + lk];
        float4 a1 = *(const float4*)&A[(size_t)(m0 + lm) * K + k0 + lk + 4];
        float4 w0 = *(const float4*)&W[(size_t)(n0 + lm) * K + k0 + lk];
        float4 w1 = *(const float4*)&W[(size_t)(n0 + lm) * K + k0 + lk + 4];
        __syncthreads();
        As[lk + 0][lm] = a0.x; As[lk + 1][lm] = a0.y; As[lk + 2][lm] = a0.z; As[lk + 3][lm] = a0.w;
        As[lk + 4][lm] = a1.x; As[lk + 5][lm] = a1.y; As[lk + 6][lm] = a1.z; As[lk + 7][lm] = a1.w;
        Ws[lk + 0][lm] = w0.x; Ws[lk + 1][lm] = w0.y; Ws[lk + 2][lm] = w0.z; Ws[lk + 3][lm] = w0.w;
        Ws[lk + 4][lm] = w1.x; Ws[lk + 5][lm] = w1.y; Ws[lk + 6][lm] = w1.z; Ws[lk + 7][lm] = w1.w;
        __syncthreads();
        #pragma unroll
        for (int k = 0; k < 16; k++) {
            float4 av0 = *(const float4*)&As[k][ty * 8];
            float4 av1 = *(const float4*)&As[k][ty * 8 + 4];
            float4 bv0 = *(const float4*)&Ws[k][tx * 8];
            float4 bv1 = *(const float4*)&Ws[k][tx * 8 + 4];
            float a8[8] = {av0.x, av0.y, av0.z, av0.w, av1.x, av1.y, av1.z, av1.w};
            float b8[8] = {bv0.x, bv0.y, bv0.z, bv0.w, bv1.x, bv1.y, bv1.z, bv1.w};
            #pragma unroll
            for (int r = 0; r < 8; r++)
                #pragma unroll
                for (int c = 0; c < 8; c++)
                    acc[r][c] = fmaf(a8[r], b8[c], acc[r][c]);
        }
    }
    #pragma unroll
    for (int r = 0; r < 8; r++) {
        int m = m0 + ty * 8 + r;
        #pragma unroll
        for (int cp = 0; cp < 2; cp++) {
            int n = n0 + tx * 8 + cp * 4;
            float4 v;
            v.x = acc[r][cp * 4 + 0] * scale; v.y = acc[r][cp * 4 + 1] * scale;
            v.z = acc[r][cp * 4 + 2] * scale; v.w = acc[r][cp * 4 + 3] * scale;
            if (bias) {
                float4 bv = *(const float4*)&bias[n];
                v.x += bv.x; v.y += bv.y; v.z += bv.z; v.w += bv.w;
            }
            *(float4*)&C[(size_t)m * N + n] = v;
        }
    }
}

// Q,K,V projections in one launch (blockIdx.z selects)
__global__ __launch_bounds__(256, 2) void proj3(
    const float* __restrict__ q_in, const float* __restrict__ k_in,
    const float* __restrict__ v_in,
    const float* __restrict__ q_w, const float* __restrict__ k_w,
    const float* __restrict__ v_w,
    float* __restrict__ gq, float* __restrict__ gk, float* __restrict__ gv)
{
    const float* A; const float* W; float* C; float scale;
    if      (blockIdx.z == 0) { A = q_in; W = q_w; C = gq; scale = 0.125f; } // dh^-0.5
    else if (blockIdx.z == 1) { A = k_in; W = k_w; C = gk; scale = 1.0f; }
    else                      { A = v_in; W = v_w; C = gv; scale = 1.0f; }
    gemm_body(A, W, nullptr, C, scale);
}

__global__ __launch_bounds__(256, 2) void out_proj(
    const float* __restrict__ A, const float* __restrict__ W,
    const float* __restrict__ bias, float* __restrict__ C)
{
    gemm_body(A, W, bias, C, 1.0f);
}

// ============== fused flash attention: online softmax + O, stores m & 1/l ===
// Block: 128 q-rows x (all t, 64 per iter), one (h,b). 256 thr, 8x4 micro.
__global__ __launch_bounds__(256, 2) void attn_fused(
    const float* __restrict__ td,
    const float* __restrict__ fa, const float* __restrict__ fb,
    const float* __restrict__ fc, const float* __restrict__ fd)
{
    extern __shared__ float4 sm4[];
    float4* Qs4 = sm4;          // 128x16 f4 = 32 KB
    float4* Ks4 = sm4 + 2048;   //  64x16 f4 = 16 KB
    float4* Vs4 = sm4 + 3072;   //  64x16 f4 = 16 KB
    float4* Ps4 = sm4 + 4096;   // 128x16 f4 = 32 KB
    float*  tq  = (float*)(sm4 + 6144);  // 128
    float*  tt  = tq + 128;              // 64

    int q0 = blockIdx.x * 128, h = blockIdx.y, b = blockIdx.z;
    int tid = threadIdx.x, tx = tid & 15, ty = tid >> 4;
    float fav = *fa, fbv = *fb, fcv = *fc, fdv = *fd;

    load_tile<128>(Qs4, g_Q + (size_t)b * E_, q0, B_ * E_, h * DH_, tid);
    if (tid < 128) tq[tid] = td[b * S_ + q0 + tid];

    float m[8], l[8], o[8][4] = {};
    #pragma unroll
    for (int r = 0; r < 8; r++) { m[r] = -1e30f; l[r] = 0.f; }

    for (int t0 = 0; t0 < S_; t0 += 64) {
        __syncthreads();
        load_tile<64>(Ks4, g_K + (size_t)b * E_, t0, B_ * E_, h * DH_, tid);
        load_tile<64>(Vs4, g_V + (size_t)b * E_, t0, B_ * E_, h * DH_, tid);
        if (tid < 64) tt[tid] = td[b * S_ + t0 + tid];
        __syncthreads();

        // S = Q @ K^T  (contract over dh=64)
        float s[8][4] = {};
        #pragma unroll
        for (int f = 0; f < 16; f++) {
            float4 bb[4];
            #pragma unroll
            for (int c = 0; c < 4; c++) bb[c] = Ks4[sw(tx * 4 + c, f)];
            #pragma unroll
            for (int r = 0; r < 8; r++) {
                float4 a = Qs4[sw(ty * 8 + r, f)];
                #pragma unroll
                for (int c = 0; c < 4; c++) {
                    s[r][c] = fmaf(a.x, bb[c].x, s[r][c]);
                    s[r][c] = fmaf(a.y, bb[c].y, s[r][c]);
                    s[r][c] = fmaf(a.z, bb[c].z, s[r][c]);
                    s[r][c] = fmaf(a.w, bb[c].w, s[r][c]);
                }
            }
        }
        // forget factor + online softmax update
        #pragma unroll
        for (int r = 0; r < 8; r++) {
            float tqv = tq[ty * 8 + r];
            #pragma unroll
            for (int c = 0; c < 4; c++) {
                float fct = fcv * __fdividef(fbv, tqv - tt[tx * 4 + c] + fav) + fdv;
                s[r][c] *= fct;
            }
            float mx = fmaxf(fmaxf(s[r][0], s[r][1]), fmaxf(s[r][2], s[r][3]));
            #pragma unroll
            for (int off = 8; off > 0; off >>= 1)
                mx = fmaxf(mx, __shfl_xor_sync(0xffffffffu, mx, off));
            float mnew = fmaxf(m[r], mx);
            float al = __expf(m[r] - mnew);
            float p0 = __expf(s[r][0] - mnew), p1 = __expf(s[r][1] - mnew);
            float p2 = __expf(s[r][2] - mnew), p3 = __expf(s[r][3] - mnew);
            float ps = p0 + p1 + p2 + p3;
            #pragma unroll
            for (int off = 8; off > 0; off >>= 1)
                ps += __shfl_xor_sync(0xffffffffu, ps, off);
            l[r] = l[r] * al + ps;
            o[r][0] *= al; o[r][1] *= al; o[r][2] *= al; o[r][3] *= al;
            m[r] = mnew;
            Ps4[sw(ty * 8 + r, tx)] = make_float4(p0, p1, p2, p3);
        }
        __syncthreads();
        // O += P @ V  (contract over j = t-rows)
        #pragma unroll
        for (int f = 0; f < 16; f++) {
            float4 p[8];
            #pragma unroll
            for (int r = 0; r < 8; r++) p[r] = Ps4[sw(ty * 8 + r, f)];
            #pragma unroll
            for (int comp = 0; comp < 4; comp++) {
                int j = f * 4 + comp;
                float4 v = Vs4[sw(j, tx)];
                #pragma unroll
                for (int r = 0; r < 8; r++) {
                    float pj = (comp == 0) ? p[r].x : (comp == 1) ? p[r].y
                             : (comp == 2) ? p[r].z : p[r].w;
                    o[r][0] = fmaf(pj, v.x, o[r][0]);
                    o[r][1] = fmaf(pj, v.y, o[r][1]);
                    o[r][2] = fmaf(pj, v.z, o[r][2]);
                    o[r][3] = fmaf(pj, v.w, o[r][3]);
                }
            }
        }
    }

    #pragma unroll
    for (int r = 0; r < 8; r++) {
        float il = 1.0f / l[r];
        int srow = q0 + ty * 8 + r;
        float4 v;
        v.x = o[r][0] * il; v.y = o[r][1] * il; v.z = o[r][2] * il; v.w = o[r][3] * il;
        *(float4*)&g_attn[((size_t)srow * B_ + b) * E_ + h * DH_ + tx * 4] = v;
        if (tx == 0) {
            g_m [((size_t)b * H_ + h) * S_ + srow] = m[r];
            g_il[((size_t)b * H_ + h) * S_ + srow] = il;
        }
    }
}

// ================= avg_w[b,s,t] = (1/H) sum_h softmax weights ================
// Block: 128 q x 64 t, loops all 16 heads, avg acc in registers. 8x4 micro.
__global__ __launch_bounds__(256, 2) void attn_avg(
    const float* __restrict__ td,
    const float* __restrict__ fa, const float* __restrict__ fb,
    const float* __restrict__ fc, const float* __restrict__ fd,
    float* __restrict__ avgw)
{
    extern __shared__ float4 sm4[];
    float4* Qs4 = sm4;          // 128x16 f4 = 32 KB
    float4* Ks4 = sm4 + 2048;   //  64x16 f4 = 16 KB
    float*  tq  = (float*)(sm4 + 3072);  // 128
    float*  tt  = tq + 128;              // 64

    int t0 = blockIdx.x * 64, q0 = blockIdx.y * 128, b = blockIdx.z;
    int tid = threadIdx.x, tx = tid & 15, ty = tid >> 4;
    float fav = *fa, fbv = *fb, fcv = *fc, fdv = *fd;

    if (tid < 128)      tq[tid]       = td[b * S_ + q0 + tid];
    else if (tid < 192) tt[tid - 128] = td[b * S_ + t0 + tid - 128];

    float aacc[8][4] = {};
    for (int h = 0; h < H_; h++) {
        __syncthreads();
        load_tile<128>(Qs4, g_Q + (size_t)b * E_, q0, B_ * E_, h * DH_, tid);
        load_tile<64> (Ks4, g_K + (size_t)b * E_, t0, B_ * E_, h * DH_, tid);
        __syncthreads();

        float s[8][4] = {};
        #pragma unroll
        for (int f = 0; f < 16; f++) {
            float4 bb[4];
            #pragma unroll
            for (int c = 0; c < 4; c++) bb[c] = Ks4[sw(tx * 4 + c, f)];
            #pragma unroll
            for (int r = 0; r < 8; r++) {
                float4 a = Qs4[sw(ty * 8 + r, f)];
                #pragma unroll
                for (int c = 0; c < 4; c++) {
                    s[r][c] = fmaf(a.x, bb[c].x, s[r][c]);
                    s[r][c] = fmaf(a.y, bb[c].y, s[r][c]);
                    s[r][c] = fmaf(a.z, bb[c].z, s[r][c]);
                    s[r][c] = fmaf(a.w, bb[c].w, s[r][c]);
                }
            }
        }
        #pragma unroll
        for (int r = 0; r < 8; r++) {
            int srow = q0 + ty * 8 + r;
            float mv = g_m [((size_t)b * H_ + h) * S_ + srow];
            float il = g_il[((size_t)b * H_ + h) * S_ + srow];
            float tqv = tq[ty * 8 + r];
            #pragma unroll
            for (int c = 0; c < 4; c++) {
                float fct = fcv * __fdividef(fbv, tqv - tt[tx * 4 + c] + fav) + fdv;
                aacc[r][c] += __expf(s[r][c] * fct - mv) * il;
            }
        }
    }
    const float invH = 1.0f / (float)H_;
    #pragma unroll
    for (int r = 0; r < 8; r++) {
        int srow = q0 + ty * 8 + r;
        float4 v;
        v.x = aacc[r][0] * invH; v.y = aacc[r][1] * invH;
        v.z = aacc[r][2] * invH; v.w = aacc[r][3] * invH;
        *(float4*)&avgw[((size_t)b * S_ + srow) * S_ + t0 + tx * 4] = v;
    }
}

// ---------------------------------------------------------------------------
extern "C" void kernel_launch(void* const* d_in, const int* in_sizes, int n_in,
                              void* d_out, int out_size)
{
    const float* query = (const float*)d_in[0];
    const float* key_t = (const float*)d_in[1];
    const float* value = (const float*)d_in[2];
    const float* td    = (const float*)d_in[3];
    const float* q_w   = (const float*)d_in[4];
    const float* k_w   = (const float*)d_in[5];
    const float* v_w   = (const float*)d_in[6];
    const float* out_w = (const float*)d_in[7];
    const float* out_b = (const float*)d_in[8];
    const float* fa    = (const float*)d_in[9];
    const float* fb    = (const float*)d_in[10];
    const float* fc    = (const float*)d_in[11];
    const float* fd    = (const float*)d_in[12];

    float* Z    = (float*)d_out;                        // [S,B,E]
    float* avgw = (float*)d_out + (size_t)S_ * B_ * E_; // [B,S,S]

    float *gQ, *gK, *gV, *gA;
    cudaGetSymbolAddress((void**)&gQ, g_Q);
    cudaGetSymbolAddress((void**)&gK, g_K);
    cudaGetSymbolAddress((void**)&gV, g_V);
    cudaGetSymbolAddress((void**)&gA, g_attn);

    const int smem_fused = 6144 * 16 + 192 * 4;  // 99072 B
    const int smem_avg   = 3072 * 16 + 192 * 4;  // 49920 B
    cudaFuncSetAttribute(attn_fused, cudaFuncAttributeMaxDynamicSharedMemorySize, smem_fused);
    cudaFuncSetAttribute(attn_avg,   cudaFuncAttributeMaxDynamicSharedMemorySize, smem_avg);

    // Q,K,V projections (one launch, z selects)
    proj3<<<dim3(E_ / 128, MR_ / 128, 3), 256>>>(query, key_t, value,
                                                 q_w, k_w, v_w, gQ, gK, gV);
    // fused flash attention (writes g_attn, g_m, g_il)
    attn_fused<<<dim3(S_ / 128, H_, B_), 256, smem_fused>>>(td, fa, fb, fc, fd);
    // output projection
    out_proj<<<dim3(E_ / 128, MR_ / 128), 256>>>(gA, out_w, out_b, Z);
    // head-averaged attention weights
    attn_avg<<<dim3(S_ / 64, S_ / 128, B_), 256, smem_avg>>>(td, fa, fb, fc, fd, avgw);
}

// round 5
// speedup vs baseline: 2.8088x; 1.2457x over previous
#include <cuda_runtime.h>
#include <cstdint>

static constexpr int S_  = 2048;
static constexpr int B_  = 2;
static constexpr int E_  = 1024;
static constexpr int H_  = 16;
static constexpr int DH_ = 64;
static constexpr int MR_ = S_ * B_;   // 4096

// ---------------- scratch (device globals: no allocations allowed) ----------
__device__ float g_Q[MR_ * E_];
__device__ float g_K[MR_ * E_];
__device__ float g_V[MR_ * E_];
__device__ float g_attn[MR_ * E_];
__device__ float g_m [B_ * H_ * S_];
__device__ float g_il[B_ * H_ * S_];
__device__ float g_S[(size_t)B_ * H_ * S_ * S_];   // post-forget scores, 512 MB

// XOR swizzle over [rows][16 float4]: conflict-free for both broadcast and
// per-lane-distinct float4 access patterns.
__device__ __forceinline__ int sw(int r, int f) { return r * 16 + (f ^ (r & 15)); }

template<int ROWS>
__device__ __forceinline__ void load_tile(float4* dst, const float* __restrict__ src,
                                          int row0, int rowStride, int colBase, int tid)
{
    #pragma unroll
    for (int idx = tid; idx < ROWS * 16; idx += 256) {
        int r = idx >> 4, f = idx & 15;
        dst[sw(r, f)] = *(const float4*)&src[(size_t)(row0 + r) * rowStride + colBase + f * 4];
    }
}

// ======================= 128x128x(K) SGEMM: C = scale*(A @ W^T) + bias ======
// A:[M,K] row-major, W:[N,K] row-major. 256 threads, 8x8 micro, k-tile 16.
__device__ __forceinline__ void gemm_body(const float* __restrict__ A,
                                          const float* __restrict__ W,
                                          const float* __restrict__ bias,
                                          float* __restrict__ C, float scale)
{
    __shared__ float As[16][132];
    __shared__ float Ws[16][132];
    const int K = E_, N = E_;
    int tid = threadIdx.x, tx = tid & 15, ty = tid >> 4;
    int m0 = blockIdx.y * 128, n0 = blockIdx.x * 128;
    int lm = tid >> 1, lk = (tid & 1) * 8;

    float acc[8][8] = {};
    for (int k0 = 0; k0 < K; k0 += 16) {
        float4 a0 = *(const float4*)&A[(size_t)(m0 + lm) * K + k0 + lk];
        float4 a1 = *(const float4*)&A[(size_t)(m0 + lm) * K + k0 + lk + 4];
        float4 w0 = *(const float4*)&W[(size_t)(n0 + lm) * K + k0 + lk];
        float4 w1 = *(const float4*)&W[(size_t)(n0 + lm) * K + k0 + lk + 4];
        __syncthreads();
        As[lk + 0][lm] = a0.x; As[lk + 1][lm] = a0.y; As[lk + 2][lm] = a0.z; As[lk + 3][lm] = a0.w;
        As[lk + 4][lm] = a1.x; As[lk + 5][lm] = a1.y; As[lk + 6][lm] = a1.z; As[lk + 7][lm] = a1.w;
        Ws[lk + 0][lm] = w0.x; Ws[lk + 1][lm] = w0.y; Ws[lk + 2][lm] = w0.z; Ws[lk + 3][lm] = w0.w;
        Ws[lk + 4][lm] = w1.x; Ws[lk + 5][lm] = w1.y; Ws[lk + 6][lm] = w1.z; Ws[lk + 7][lm] = w1.w;
        __syncthreads();
        #pragma unroll
        for (int k = 0; k < 16; k++) {
            float4 av0 = *(const float4*)&As[k][ty * 8];
            float4 av1 = *(const float4*)&As[k][ty * 8 + 4];
            float4 bv0 = *(const float4*)&Ws[k][tx * 8];
            float4 bv1 = *(const float4*)&Ws[k][tx * 8 + 4];
            float a8[8] = {av0.x, av0.y, av0.z, av0.w, av1.x, av1.y, av1.z, av1.w};
            float b8[8] = {bv0.x, bv0.y, bv0.z, bv0.w, bv1.x, bv1.y, bv1.z, bv1.w};
            #pragma unroll
            for (int r = 0; r < 8; r++)
                #pragma unroll
                for (int c = 0; c < 8; c++)
                    acc[r][c] = fmaf(a8[r], b8[c], acc[r][c]);
        }
    }
    #pragma unroll
    for (int r = 0; r < 8; r++) {
        int m = m0 + ty * 8 + r;
        #pragma unroll
        for (int cp = 0; cp < 2; cp++) {
            int n = n0 + tx * 8 + cp * 4;
            float4 v;
            v.x = acc[r][cp * 4 + 0] * scale; v.y = acc[r][cp * 4 + 1] * scale;
            v.z = acc[r][cp * 4 + 2] * scale; v.w = acc[r][cp * 4 + 3] * scale;
            if (bias) {
                float4 bv = *(const float4*)&bias[n];
                v.x += bv.x; v.y += bv.y; v.z += bv.z; v.w += bv.w;
            }
            *(float4*)&C[(size_t)m * N + n] = v;
        }
    }
}

__global__ __launch_bounds__(256, 2) void proj3(
    const float* __restrict__ q_in, const float* __restrict__ k_in,
    const float* __restrict__ v_in,
    const float* __restrict__ q_w, const float* __restrict__ k_w,
    const float* __restrict__ v_w,
    float* __restrict__ gq, float* __restrict__ gk, float* __restrict__ gv)
{
    const float* A; const float* W; float* C; float scale;
    if      (blockIdx.z == 0) { A = q_in; W = q_w; C = gq; scale = 0.125f; } // dh^-0.5
    else if (blockIdx.z == 1) { A = k_in; W = k_w; C = gk; scale = 1.0f; }
    else                      { A = v_in; W = v_w; C = gv; scale = 1.0f; }
    gemm_body(A, W, nullptr, C, scale);
}

__global__ __launch_bounds__(256, 2) void out_proj(
    const float* __restrict__ A, const float* __restrict__ W,
    const float* __restrict__ bias, float* __restrict__ C)
{
    gemm_body(A, W, bias, C, 1.0f);
}

// ============== fused flash attention: online softmax + O + score stash =====
// Block: 128 q-rows x (all t, 64 per iter), one (h,b). 256 thr, 8x4 micro.
__global__ __launch_bounds__(256, 2) void attn_fused(
    const float* __restrict__ td,
    const float* __restrict__ fa, const float* __restrict__ fb,
    const float* __restrict__ fc, const float* __restrict__ fd)
{
    extern __shared__ float4 sm4[];
    float4* Qs4 = sm4;          // 128x16 f4 = 32 KB
    float4* Ks4 = sm4 + 2048;   //  64x16 f4 = 16 KB
    float4* Vs4 = sm4 + 3072;   //  64x16 f4 = 16 KB
    float4* Ps4 = sm4 + 4096;   // 128x16 f4 = 32 KB
    float*  tq  = (float*)(sm4 + 6144);  // 128
    float*  tt  = tq + 128;              // 64

    int q0 = blockIdx.x * 128, h = blockIdx.y, b = blockIdx.z;
    int tid = threadIdx.x, tx = tid & 15, ty = tid >> 4;
    float fav = *fa, fbv = *fb, fcv = *fc, fdv = *fd;

    load_tile<128>(Qs4, g_Q + (size_t)b * E_, q0, B_ * E_, h * DH_, tid);
    if (tid < 128) tq[tid] = td[b * S_ + q0 + tid];

    float m[8], l[8], o[8][4] = {};
    #pragma unroll
    for (int r = 0; r < 8; r++) { m[r] = -1e30f; l[r] = 0.f; }

    float* Sbase = g_S + ((size_t)(b * H_ + h) * S_) * S_;

    for (int t0 = 0; t0 < S_; t0 += 64) {
        __syncthreads();
        load_tile<64>(Ks4, g_K + (size_t)b * E_, t0, B_ * E_, h * DH_, tid);
        load_tile<64>(Vs4, g_V + (size_t)b * E_, t0, B_ * E_, h * DH_, tid);
        if (tid < 64) tt[tid] = td[b * S_ + t0 + tid];
        __syncthreads();

        // S = Q @ K^T  (contract over dh=64)
        float s[8][4] = {};
        #pragma unroll
        for (int f = 0; f < 16; f++) {
            float4 bb[4];
            #pragma unroll
            for (int c = 0; c < 4; c++) bb[c] = Ks4[sw(tx * 4 + c, f)];
            #pragma unroll
            for (int r = 0; r < 8; r++) {
                float4 a = Qs4[sw(ty * 8 + r, f)];
                #pragma unroll
                for (int c = 0; c < 4; c++) {
                    s[r][c] = fmaf(a.x, bb[c].x, s[r][c]);
                    s[r][c] = fmaf(a.y, bb[c].y, s[r][c]);
                    s[r][c] = fmaf(a.z, bb[c].z, s[r][c]);
                    s[r][c] = fmaf(a.w, bb[c].w, s[r][c]);
                }
            }
        }
        // forget factor, stash scores for the avg pass, online softmax update
        #pragma unroll
        for (int r = 0; r < 8; r++) {
            int srow = q0 + ty * 8 + r;
            float tqv = tq[ty * 8 + r];
            #pragma unroll
            for (int c = 0; c < 4; c++) {
                float fct = fcv * __fdividef(fbv, tqv - tt[tx * 4 + c] + fav) + fdv;
                s[r][c] *= fct;
            }
            *(float4*)&Sbase[(size_t)srow * S_ + t0 + tx * 4] =
                make_float4(s[r][0], s[r][1], s[r][2], s[r][3]);

            float mx = fmaxf(fmaxf(s[r][0], s[r][1]), fmaxf(s[r][2], s[r][3]));
            #pragma unroll
            for (int off = 8; off > 0; off >>= 1)
                mx = fmaxf(mx, __shfl_xor_sync(0xffffffffu, mx, off));
            float mnew = fmaxf(m[r], mx);
            float al = __expf(m[r] - mnew);
            float p0 = __expf(s[r][0] - mnew), p1 = __expf(s[r][1] - mnew);
            float p2 = __expf(s[r][2] - mnew), p3 = __expf(s[r][3] - mnew);
            float ps = p0 + p1 + p2 + p3;
            #pragma unroll
            for (int off = 8; off > 0; off >>= 1)
                ps += __shfl_xor_sync(0xffffffffu, ps, off);
            l[r] = l[r] * al + ps;
            o[r][0] *= al; o[r][1] *= al; o[r][2] *= al; o[r][3] *= al;
            m[r] = mnew;
            Ps4[sw(ty * 8 + r, tx)] = make_float4(p0, p1, p2, p3);
        }
        __syncthreads();
        // O += P @ V  (contract over j = t-rows)
        #pragma unroll
        for (int f = 0; f < 16; f++) {
            float4 p[8];
            #pragma unroll
            for (int r = 0; r < 8; r++) p[r] = Ps4[sw(ty * 8 + r, f)];
            #pragma unroll
            for (int comp = 0; comp < 4; comp++) {
                int j = f * 4 + comp;
                float4 v = Vs4[sw(j, tx)];
                #pragma unroll
                for (int r = 0; r < 8; r++) {
                    float pj = (comp == 0) ? p[r].x : (comp == 1) ? p[r].y
                             : (comp == 2) ? p[r].z : p[r].w;
                    o[r][0] = fmaf(pj, v.x, o[r][0]);
                    o[r][1] = fmaf(pj, v.y, o[r][1]);
                    o[r][2] = fmaf(pj, v.z, o[r][2]);
                    o[r][3] = fmaf(pj, v.w, o[r][3]);
                }
            }
        }
    }

    #pragma unroll
    for (int r = 0; r < 8; r++) {
        float il = 1.0f / l[r];
        int srow = q0 + ty * 8 + r;
        float4 v;
        v.x = o[r][0] * il; v.y = o[r][1] * il; v.z = o[r][2] * il; v.w = o[r][3] * il;
        *(float4*)&g_attn[((size_t)srow * B_ + b) * E_ + h * DH_ + tx * 4] = v;
        if (tx == 0) {
            g_m [((size_t)b * H_ + h) * S_ + srow] = m[r];
            g_il[((size_t)b * H_ + h) * S_ + srow] = il;
        }
    }
}

// ====== avg_w[b,s,t] = (1/H) sum_h exp(S[b,h,s,t]-m)·il : streaming pass =====
__global__ __launch_bounds__(256) void attn_avg2(float* __restrict__ avgw)
{
    __shared__ float ms[H_], ils[H_];
    int s = blockIdx.x, b = blockIdx.y;
    int tid = threadIdx.x;
    if (tid < H_) {
        ms[tid]  = g_m [((size_t)b * H_ + tid) * S_ + s];
        ils[tid] = g_il[((size_t)b * H_ + tid) * S_ + s];
    }
    __syncthreads();

    float4 a0 = {0, 0, 0, 0}, a1 = {0, 0, 0, 0};
    #pragma unroll 4
    for (int h = 0; h < H_; h++) {
        const float4* row = (const float4*)&g_S[(((size_t)b * H_ + h) * S_ + s) * S_];
        float4 v0 = row[tid], v1 = row[tid + 256];
        float mh = ms[h], ih = ils[h];
        a0.x += __expf(v0.x - mh) * ih; a0.y += __expf(v0.y - mh) * ih;
        a0.z += __expf(v0.z - mh) * ih; a0.w += __expf(v0.w - mh) * ih;
        a1.x += __expf(v1.x - mh) * ih; a1.y += __expf(v1.y - mh) * ih;
        a1.z += __expf(v1.z - mh) * ih; a1.w += __expf(v1.w - mh) * ih;
    }
    const float invH = 1.0f / (float)H_;
    float4* out = (float4*)&avgw[((size_t)b * S_ + s) * S_];
    a0.x *= invH; a0.y *= invH; a0.z *= invH; a0.w *= invH;
    a1.x *= invH; a1.y *= invH; a1.z *= invH; a1.w *= invH;
    out[tid] = a0;
    out[tid + 256] = a1;
}

// ---------------------------------------------------------------------------
extern "C" void kernel_launch(void* const* d_in, const int* in_sizes, int n_in,
                              void* d_out, int out_size)
{
    const float* query = (const float*)d_in[0];
    const float* key_t = (const float*)d_in[1];
    const float* value = (const float*)d_in[2];
    const float* td    = (const float*)d_in[3];
    const float* q_w   = (const float*)d_in[4];
    const float* k_w   = (const float*)d_in[5];
    const float* v_w   = (const float*)d_in[6];
    const float* out_w = (const float*)d_in[7];
    const float* out_b = (const float*)d_in[8];
    const float* fa    = (const float*)d_in[9];
    const float* fb    = (const float*)d_in[10];
    const float* fc    = (const float*)d_in[11];
    const float* fd    = (const float*)d_in[12];

    float* Z    = (float*)d_out;                        // [S,B,E]
    float* avgw = (float*)d_out + (size_t)S_ * B_ * E_; // [B,S,S]

    float *gQ, *gK, *gV, *gA;
    cudaGetSymbolAddress((void**)&gQ, g_Q);
    cudaGetSymbolAddress((void**)&gK, g_K);
    cudaGetSymbolAddress((void**)&gV, g_V);
    cudaGetSymbolAddress((void**)&gA, g_attn);

    const int smem_fused = 6144 * 16 + 192 * 4;  // 99072 B
    cudaFuncSetAttribute(attn_fused, cudaFuncAttributeMaxDynamicSharedMemorySize, smem_fused);

    // Q,K,V projections (one launch, z selects)
    proj3<<<dim3(E_ / 128, MR_ / 128, 3), 256>>>(query, key_t, value,
                                                 q_w, k_w, v_w, gQ, gK, gV);
    // fused flash attention (writes g_attn, g_m, g_il, g_S)
    attn_fused<<<dim3(S_ / 128, H_, B_), 256, smem_fused>>>(td, fa, fb, fc, fd);
    // output projection
    out_proj<<<dim3(E_ / 128, MR_ / 128), 256>>>(gA, out_w, out_b, Z);
    // head-averaged weights: stream stored scores
    attn_avg2<<<dim3(S_, B_), 256>>>(avgw);
}

// round 6
// speedup vs baseline: 3.2835x; 1.1690x over previous
#include <cuda_runtime.h>
#include <cuda_bf16.h>
#include <cstdint>

static constexpr int S_  = 2048;
static constexpr int B_  = 2;
static constexpr int E_  = 1024;
static constexpr int H_  = 16;
static constexpr int DH_ = 64;
static constexpr int MR_ = S_ * B_;   // 4096

// ---------------- scratch (device globals: no allocations allowed) ----------
__device__ float g_Q[MR_ * E_];
__device__ float g_K[MR_ * E_];
__device__ float g_V[MR_ * E_];
__device__ float g_attn[MR_ * E_];
__device__ float g_m [B_ * H_ * S_];
__device__ float g_il[B_ * H_ * S_];
__device__ float g_S[(size_t)B_ * H_ * S_ * S_];   // post-forget scores, 512 MB

// ===================== mma.sync helpers (sm_80 baseline PTX) =================
__device__ __forceinline__ uint32_t smem_u32(const void* p) {
    uint32_t a;
    asm("{ .reg .u64 t; cvta.to.shared.u64 t, %1; cvt.u32.u64 %0, t; }" : "=r"(a) : "l"(p));
    return a;
}
__device__ __forceinline__ void ldsm4(uint32_t* r, uint32_t addr) {
    asm volatile("ldmatrix.sync.aligned.m8n8.x4.shared.b16 {%0,%1,%2,%3}, [%4];"
                 : "=r"(r[0]), "=r"(r[1]), "=r"(r[2]), "=r"(r[3]) : "r"(addr));
}
__device__ __forceinline__ void mma_bf16(float* c, const uint32_t* a, uint32_t b0, uint32_t b1) {
    asm volatile("mma.sync.aligned.m16n8k16.row.col.f32.bf16.bf16.f32 "
                 "{%0,%1,%2,%3}, {%4,%5,%6,%7}, {%8,%9}, {%0,%1,%2,%3};"
                 : "+f"(c[0]), "+f"(c[1]), "+f"(c[2]), "+f"(c[3])
                 : "r"(a[0]), "r"(a[1]), "r"(a[2]), "r"(a[3]), "r"(b0), "r"(b1));
}
// split 8 fp32 -> 8 bf16 hi + 8 bf16 lo, store as two STS.128
__device__ __forceinline__ void cvt_store8(uint32_t dhi, uint32_t dlo, float4 v0, float4 v1) {
    float x[8] = {v0.x, v0.y, v0.z, v0.w, v1.x, v1.y, v1.z, v1.w};
    uint32_t hi[4], lo[4];
    #pragma unroll
    for (int p = 0; p < 4; p++) {
        __nv_bfloat16 h0 = __float2bfloat16(x[2*p]);
        __nv_bfloat16 h1 = __float2bfloat16(x[2*p+1]);
        __nv_bfloat16 l0 = __float2bfloat16(x[2*p]   - __bfloat162float(h0));
        __nv_bfloat16 l1 = __float2bfloat16(x[2*p+1] - __bfloat162float(h1));
        hi[p] = (uint32_t)__bfloat16_as_ushort(h0) | ((uint32_t)__bfloat16_as_ushort(h1) << 16);
        lo[p] = (uint32_t)__bfloat16_as_ushort(l0) | ((uint32_t)__bfloat16_as_ushort(l1) << 16);
    }
    asm volatile("st.shared.v4.b32 [%0], {%1,%2,%3,%4};"
                 :: "r"(dhi), "r"(hi[0]), "r"(hi[1]), "r"(hi[2]), "r"(hi[3]) : "memory");
    asm volatile("st.shared.v4.b32 [%0], {%1,%2,%3,%4};"
                 :: "r"(dlo), "r"(lo[0]), "r"(lo[1]), "r"(lo[2]), "r"(lo[3]) : "memory");
}

// ====== bf16x3 tensor-core GEMM: C[128x128 tile] = scale*(A @ W^T) + bias ====
// A:[M,1024] fp32, W:[1024,1024] fp32 (row-major, N rows of K). 512 threads.
// smem: Ah(6KB) Al(6KB) Wh(6KB) Wl(6KB); rows of 16 bf16, 48B stride.
__device__ __forceinline__ void gemm_mma_body(
    const float* __restrict__ A, const float* __restrict__ W,
    const float* __restrict__ bias, float* __restrict__ C, float scale)
{
    __shared__ __align__(16) unsigned char smb[4 * 6144];
    const int tid = threadIdx.x, lane = tid & 31, wid = tid >> 5;
    const int wm = wid & 3, wn = wid >> 2;          // 4x4 warp grid, m32n32 each
    const int m0 = blockIdx.y * 128, n0 = blockIdx.x * 128;
    const uint32_t sb = smem_u32(smb);
    const uint32_t AH = 0, AL = 6144, WH = 12288, WL = 18432;

    // convert-phase role: tid<256 -> A rows, else W rows; one half-row each
    const float* csrc = (tid < 256) ? A : W;
    const int crow = (tid & 255) >> 1, ch = tid & 1;
    const int grow = ((tid < 256) ? m0 : n0) + crow;
    const uint32_t dhi = sb + ((tid < 256) ? AH : WH) + crow * 48 + ch * 16;
    const uint32_t dlo = dhi + 6144;
    const float* gsrc = csrc + (size_t)grow * E_ + ch * 8;

    // fixed ldmatrix addresses
    const int lr = lane & 15, lkh = lane >> 4;
    uint32_t aAddr[2], wAddr[2];
    aAddr[0] = sb + AH + (wm * 32 +  0 + lr) * 48 + lkh * 16;
    aAddr[1] = sb + AH + (wm * 32 + 16 + lr) * 48 + lkh * 16;
    wAddr[0] = sb + WH + (wn * 32 +  0 + lr) * 48 + lkh * 16;
    wAddr[1] = sb + WH + (wn * 32 + 16 + lr) * 48 + lkh * 16;

    float acc[2][4][4] = {};

    // prefetch k-chunk 0, convert, store
    float4 pv0 = *(const float4*)gsrc;
    float4 pv1 = *(const float4*)(gsrc + 4);
    cvt_store8(dhi, dlo, pv0, pv1);
    __syncthreads();

    for (int kb = 0; kb < 64; kb++) {
        if (kb < 63) {                       // prefetch next chunk (overlaps MMA)
            const float* g = gsrc + (kb + 1) * 16;
            pv0 = *(const float4*)g;
            pv1 = *(const float4*)(g + 4);
        }
        uint32_t aH[2][4], aL[2][4], wH[2][4], wL[2][4];
        ldsm4(aH[0], aAddr[0]);        ldsm4(aH[1], aAddr[1]);
        ldsm4(aL[0], aAddr[0] + 6144); ldsm4(aL[1], aAddr[1] + 6144);
        ldsm4(wH[0], wAddr[0]);        ldsm4(wH[1], wAddr[1]);
        ldsm4(wL[0], wAddr[0] + 6144); ldsm4(wL[1], wAddr[1] + 6144);
        #pragma unroll
        for (int i = 0; i < 2; i++)
            #pragma unroll
            for (int j = 0; j < 4; j++) {
                int jj = j >> 1, js = j & 1;
                uint32_t b0h = wH[jj][js], b1h = wH[jj][js + 2];
                uint32_t b0l = wL[jj][js], b1l = wL[jj][js + 2];
                mma_bf16(acc[i][j], aH[i], b0h, b1h);   // hi*hi
                mma_bf16(acc[i][j], aH[i], b0l, b1l);   // hi*lo
                mma_bf16(acc[i][j], aL[i], b0h, b1h);   // lo*hi
            }
        __syncthreads();
        if (kb < 63) cvt_store8(dhi, dlo, pv0, pv1);
        __syncthreads();
    }

    // epilogue: c0,c1 = (row, col 2*(lane&3)+{0,1}); c2,c3 = row+8
    #pragma unroll
    for (int i = 0; i < 2; i++) {
        int mrow = m0 + wm * 32 + i * 16 + (lane >> 2);
        #pragma unroll
        for (int j = 0; j < 4; j++) {
            int n = n0 + wn * 32 + j * 8 + (lane & 3) * 2;
            float bx = 0.f, by = 0.f;
            if (bias) { float2 bv = *(const float2*)&bias[n]; bx = bv.x; by = bv.y; }
            float2 v0 = {acc[i][j][0] * scale + bx, acc[i][j][1] * scale + by};
            float2 v1 = {acc[i][j][2] * scale + bx, acc[i][j][3] * scale + by};
            *(float2*)&C[(size_t)mrow * E_ + n]       = v0;
            *(float2*)&C[(size_t)(mrow + 8) * E_ + n] = v1;
        }
    }
}

__global__ __launch_bounds__(512) void proj3_mma(
    const float* __restrict__ q_in, const float* __restrict__ k_in,
    const float* __restrict__ v_in,
    const float* __restrict__ q_w, const float* __restrict__ k_w,
    const float* __restrict__ v_w,
    float* __restrict__ gq, float* __restrict__ gk, float* __restrict__ gv)
{
    if      (blockIdx.z == 0) gemm_mma_body(q_in, q_w, nullptr, gq, 0.125f); // dh^-0.5
    else if (blockIdx.z == 1) gemm_mma_body(k_in, k_w, nullptr, gk, 1.0f);
    else                      gemm_mma_body(v_in, v_w, nullptr, gv, 1.0f);
}

__global__ __launch_bounds__(512) void outproj_mma(
    const float* __restrict__ A, const float* __restrict__ W,
    const float* __restrict__ bias, float* __restrict__ C)
{
    gemm_mma_body(A, W, bias, C, 1.0f);
}

// ================== fused flash attention (SIMT, fp32) =======================
__device__ __forceinline__ int sw(int r, int f) { return r * 16 + (f ^ (r & 15)); }

template<int ROWS>
__device__ __forceinline__ void load_tile(float4* dst, const float* __restrict__ src,
                                          int row0, int rowStride, int colBase, int tid)
{
    #pragma unroll
    for (int idx = tid; idx < ROWS * 16; idx += 256) {
        int r = idx >> 4, f = idx & 15;
        dst[sw(r, f)] = *(const float4*)&src[(size_t)(row0 + r) * rowStride + colBase + f * 4];
    }
}

__global__ __launch_bounds__(256, 2) void attn_fused(
    const float* __restrict__ td,
    const float* __restrict__ fa, const float* __restrict__ fb,
    const float* __restrict__ fc, const float* __restrict__ fd)
{
    extern __shared__ float4 sm4[];
    float4* Qs4 = sm4;          // 128x16 f4 = 32 KB
    float4* Ks4 = sm4 + 2048;   //  64x16 f4 = 16 KB
    float4* Vs4 = sm4 + 3072;   //  64x16 f4 = 16 KB
    float4* Ps4 = sm4 + 4096;   // 128x16 f4 = 32 KB
    float*  tq  = (float*)(sm4 + 6144);  // 128
    float*  tt  = tq + 128;              // 64

    int q0 = blockIdx.x * 128, h = blockIdx.y, b = blockIdx.z;
    int tid = threadIdx.x, tx = tid & 15, ty = tid >> 4;
    float fav = *fa, fbv = *fb, fcv = *fc, fdv = *fd;

    load_tile<128>(Qs4, g_Q + (size_t)b * E_, q0, B_ * E_, h * DH_, tid);
    if (tid < 128) tq[tid] = td[b * S_ + q0 + tid];

    float m[8], l[8], o[8][4] = {};
    #pragma unroll
    for (int r = 0; r < 8; r++) { m[r] = -1e30f; l[r] = 0.f; }

    float* Sbase = g_S + ((size_t)(b * H_ + h) * S_) * S_;

    for (int t0 = 0; t0 < S_; t0 += 64) {
        __syncthreads();
        load_tile<64>(Ks4, g_K + (size_t)b * E_, t0, B_ * E_, h * DH_, tid);
        load_tile<64>(Vs4, g_V + (size_t)b * E_, t0, B_ * E_, h * DH_, tid);
        if (tid < 64) tt[tid] = td[b * S_ + t0 + tid];
        __syncthreads();

        // S = Q @ K^T  (contract over dh=64)
        float s[8][4] = {};
        #pragma unroll
        for (int f = 0; f < 16; f++) {
            float4 bb[4];
            #pragma unroll
            for (int c = 0; c < 4; c++) bb[c] = Ks4[sw(tx * 4 + c, f)];
            #pragma unroll
            for (int r = 0; r < 8; r++) {
                float4 a = Qs4[sw(ty * 8 + r, f)];
                #pragma unroll
                for (int c = 0; c < 4; c++) {
                    s[r][c] = fmaf(a.x, bb[c].x, s[r][c]);
                    s[r][c] = fmaf(a.y, bb[c].y, s[r][c]);
                    s[r][c] = fmaf(a.z, bb[c].z, s[r][c]);
                    s[r][c] = fmaf(a.w, bb[c].w, s[r][c]);
                }
            }
        }
        // forget factor, stash scores for the avg pass, online softmax update
        #pragma unroll
        for (int r = 0; r < 8; r++) {
            int srow = q0 + ty * 8 + r;
            float tqv = tq[ty * 8 + r];
            #pragma unroll
            for (int c = 0; c < 4; c++) {
                float fct = fcv * __fdividef(fbv, tqv - tt[tx * 4 + c] + fav) + fdv;
                s[r][c] *= fct;
            }
            *(float4*)&Sbase[(size_t)srow * S_ + t0 + tx * 4] =
                make_float4(s[r][0], s[r][1], s[r][2], s[r][3]);

            float mx = fmaxf(fmaxf(s[r][0], s[r][1]), fmaxf(s[r][2], s[r][3]));
            #pragma unroll
            for (int off = 8; off > 0; off >>= 1)
                mx = fmaxf(mx, __shfl_xor_sync(0xffffffffu, mx, off));
            float mnew = fmaxf(m[r], mx);
            float al = __expf(m[r] - mnew);
            float p0 = __expf(s[r][0] - mnew), p1 = __expf(s[r][1] - mnew);
            float p2 = __expf(s[r][2] - mnew), p3 = __expf(s[r][3] - mnew);
            float ps = p0 + p1 + p2 + p3;
            #pragma unroll
            for (int off = 8; off > 0; off >>= 1)
                ps += __shfl_xor_sync(0xffffffffu, ps, off);
            l[r] = l[r] * al + ps;
            o[r][0] *= al; o[r][1] *= al; o[r][2] *= al; o[r][3] *= al;
            m[r] = mnew;
            Ps4[sw(ty * 8 + r, tx)] = make_float4(p0, p1, p2, p3);
        }
        __syncthreads();
        // O += P @ V  (contract over j = t-rows)
        #pragma unroll
        for (int f = 0; f < 16; f++) {
            float4 p[8];
            #pragma unroll
            for (int r = 0; r < 8; r++) p[r] = Ps4[sw(ty * 8 + r, f)];
            #pragma unroll
            for (int comp = 0; comp < 4; comp++) {
                int j = f * 4 + comp;
                float4 v = Vs4[sw(j, tx)];
                #pragma unroll
                for (int r = 0; r < 8; r++) {
                    float pj = (comp == 0) ? p[r].x : (comp == 1) ? p[r].y
                             : (comp == 2) ? p[r].z : p[r].w;
                    o[r][0] = fmaf(pj, v.x, o[r][0]);
                    o[r][1] = fmaf(pj, v.y, o[r][1]);
                    o[r][2] = fmaf(pj, v.z, o[r][2]);
                    o[r][3] = fmaf(pj, v.w, o[r][3]);
                }
            }
        }
    }

    #pragma unroll
    for (int r = 0; r < 8; r++) {
        float il = 1.0f / l[r];
        int srow = q0 + ty * 8 + r;
        float4 v;
        v.x = o[r][0] * il; v.y = o[r][1] * il; v.z = o[r][2] * il; v.w = o[r][3] * il;
        *(float4*)&g_attn[((size_t)srow * B_ + b) * E_ + h * DH_ + tx * 4] = v;
        if (tx == 0) {
            g_m [((size_t)b * H_ + h) * S_ + srow] = m[r];
            g_il[((size_t)b * H_ + h) * S_ + srow] = il;
        }
    }
}

// ====== avg_w[b,s,t] = (1/H) sum_h exp(S[b,h,s,t]-m)·il : streaming pass =====
__global__ __launch_bounds__(256) void attn_avg2(float* __restrict__ avgw)
{
    __shared__ float ms[H_], ils[H_];
    int s = blockIdx.x, b = blockIdx.y;
    int tid = threadIdx.x;
    if (tid < H_) {
        ms[tid]  = g_m [((size_t)b * H_ + tid) * S_ + s];
        ils[tid] = g_il[((size_t)b * H_ + tid) * S_ + s];
    }
    __syncthreads();

    float4 a0 = {0, 0, 0, 0}, a1 = {0, 0, 0, 0};
    #pragma unroll 4
    for (int h = 0; h < H_; h++) {
        const float4* row = (const float4*)&g_S[(((size_t)b * H_ + h) * S_ + s) * S_];
        float4 v0 = row[tid], v1 = row[tid + 256];
        float mh = ms[h], ih = ils[h];
        a0.x += __expf(v0.x - mh) * ih; a0.y += __expf(v0.y - mh) * ih;
        a0.z += __expf(v0.z - mh) * ih; a0.w += __expf(v0.w - mh) * ih;
        a1.x += __expf(v1.x - mh) * ih; a1.y += __expf(v1.y - mh) * ih;
        a1.z += __expf(v1.z - mh) * ih; a1.w += __expf(v1.w - mh) * ih;
    }
    const float invH = 1.0f / (float)H_;
    float4* out = (float4*)&avgw[((size_t)b * S_ + s) * S_];
    a0.x *= invH; a0.y *= invH; a0.z *= invH; a0.w *= invH;
    a1.x *= invH; a1.y *= invH; a1.z *= invH; a1.w *= invH;
    out[tid] = a0;
    out[tid + 256] = a1;
}

// ---------------------------------------------------------------------------
extern "C" void kernel_launch(void* const* d_in, const int* in_sizes, int n_in,
                              void* d_out, int out_size)
{
    const float* query = (const float*)d_in[0];
    const float* key_t = (const float*)d_in[1];
    const float* value = (const float*)d_in[2];
    const float* td    = (const float*)d_in[3];
    const float* q_w   = (const float*)d_in[4];
    const float* k_w   = (const float*)d_in[5];
    const float* v_w   = (const float*)d_in[6];
    const float* out_w = (const float*)d_in[7];
    const float* out_b = (const float*)d_in[8];
    const float* fa    = (const float*)d_in[9];
    const float* fb    = (const float*)d_in[10];
    const float* fc    = (const float*)d_in[11];
    const float* fd    = (const float*)d_in[12];

    float* Z    = (float*)d_out;                        // [S,B,E]
    float* avgw = (float*)d_out + (size_t)S_ * B_ * E_; // [B,S,S]

    float *gQ, *gK, *gV, *gA;
    cudaGetSymbolAddress((void**)&gQ, g_Q);
    cudaGetSymbolAddress((void**)&gK, g_K);
    cudaGetSymbolAddress((void**)&gV, g_V);
    cudaGetSymbolAddress((void**)&gA, g_attn);

    const int smem_fused = 6144 * 16 + 192 * 4;  // 99072 B
    cudaFuncSetAttribute(attn_fused, cudaFuncAttributeMaxDynamicSharedMemorySize, smem_fused);

    // Q,K,V projections (mma.sync bf16x3 tensor cores)
    proj3_mma<<<dim3(E_ / 128, MR_ / 128, 3), 512>>>(query, key_t, value,
                                                     q_w, k_w, v_w, gQ, gK, gV);
    // fused flash attention (writes g_attn, g_m, g_il, g_S)
    attn_fused<<<dim3(S_ / 128, H_, B_), 256, smem_fused>>>(td, fa, fb, fc, fd);
    // output projection (mma.sync bf16x3)
    outproj_mma<<<dim3(E_ / 128, MR_ / 128), 512>>>(gA, out_w, out_b, Z);
    // head-averaged weights: stream stored scores
    attn_avg2<<<dim3(S_, B_), 256>>>(avgw);
}

// round 7
// speedup vs baseline: 6.4517x; 1.9649x over previous
#include <cuda_runtime.h>
#include <cuda_bf16.h>
#include <cstdint>

static constexpr int S_  = 2048;
static constexpr int B_  = 2;
static constexpr int E_  = 1024;
static constexpr int H_  = 16;
static constexpr int DH_ = 64;
static constexpr int MR_ = S_ * B_;   // 4096

// ---------------- scratch (device globals: no allocations allowed) ----------
__device__ float g_Q[MR_ * E_];
__device__ float g_K[MR_ * E_];
__device__ float g_V[MR_ * E_];
__device__ float g_attn[MR_ * E_];
__device__ float g_m [B_ * H_ * S_];
__device__ float g_il[B_ * H_ * S_];
__device__ float g_S[(size_t)B_ * H_ * S_ * S_];   // post-forget scores, 512 MB

// ===================== mma.sync helpers (sm_80 baseline PTX) =================
__device__ __forceinline__ uint32_t smem_u32(const void* p) {
    uint32_t a;
    asm("{ .reg .u64 t; cvta.to.shared.u64 t, %1; cvt.u32.u64 %0, t; }" : "=r"(a) : "l"(p));
    return a;
}
__device__ __forceinline__ void ldsm4(uint32_t* r, uint32_t addr) {
    asm volatile("ldmatrix.sync.aligned.m8n8.x4.shared.b16 {%0,%1,%2,%3}, [%4];"
                 : "=r"(r[0]), "=r"(r[1]), "=r"(r[2]), "=r"(r[3]) : "r"(addr));
}
__device__ __forceinline__ void ldsm4t(uint32_t* r, uint32_t addr) {
    asm volatile("ldmatrix.sync.aligned.m8n8.x4.trans.shared.b16 {%0,%1,%2,%3}, [%4];"
                 : "=r"(r[0]), "=r"(r[1]), "=r"(r[2]), "=r"(r[3]) : "r"(addr));
}
__device__ __forceinline__ void mma_bf16(float* c, const uint32_t* a, uint32_t b0, uint32_t b1) {
    asm volatile("mma.sync.aligned.m16n8k16.row.col.f32.bf16.bf16.f32 "
                 "{%0,%1,%2,%3}, {%4,%5,%6,%7}, {%8,%9}, {%0,%1,%2,%3};"
                 : "+f"(c[0]), "+f"(c[1]), "+f"(c[2]), "+f"(c[3])
                 : "r"(a[0]), "r"(a[1]), "r"(a[2]), "r"(a[3]), "r"(b0), "r"(b1));
}
// pack two fp32 into one bf16x2 reg: elem0(lower)=lo, elem1(upper)=hi
__device__ __forceinline__ uint32_t packbf2(float lo, float hi) {
    uint32_t r;
    asm("cvt.rn.bf16x2.f32 %0, %1, %2;" : "=r"(r) : "f"(hi), "f"(lo));
    return r;
}
// split 8 fp32 -> 8 bf16 hi + 8 bf16 lo, store as two STS.128
__device__ __forceinline__ void cvt_store8(uint32_t dhi, uint32_t dlo, float4 v0, float4 v1) {
    float x[8] = {v0.x, v0.y, v0.z, v0.w, v1.x, v1.y, v1.z, v1.w};
    uint32_t hi[4], lo[4];
    #pragma unroll
    for (int p = 0; p < 4; p++) {
        uint32_t h = packbf2(x[2*p], x[2*p+1]);
        float xh = __uint_as_float(h << 16);
        float yh = __uint_as_float(h & 0xFFFF0000u);
        hi[p] = h;
        lo[p] = packbf2(x[2*p] - xh, x[2*p+1] - yh);
    }
    asm volatile("st.shared.v4.b32 [%0], {%1,%2,%3,%4};"
                 :: "r"(dhi), "r"(hi[0]), "r"(hi[1]), "r"(hi[2]), "r"(hi[3]) : "memory");
    asm volatile("st.shared.v4.b32 [%0], {%1,%2,%3,%4};"
                 :: "r"(dlo), "r"(lo[0]), "r"(lo[1]), "r"(lo[2]), "r"(lo[3]) : "memory");
}

// ====== bf16x3 tensor-core GEMM: C[128x128 tile] = scale*(A @ W^T) + bias ====
__device__ __forceinline__ void gemm_mma_body(
    const float* __restrict__ A, const float* __restrict__ W,
    const float* __restrict__ bias, float* __restrict__ C, float scale)
{
    __shared__ __align__(16) unsigned char smb[4 * 6144];
    const int tid = threadIdx.x, lane = tid & 31, wid = tid >> 5;
    const int wm = wid & 3, wn = wid >> 2;
    const int m0 = blockIdx.y * 128, n0 = blockIdx.x * 128;
    const uint32_t sb = smem_u32(smb);
    const uint32_t AH = 0, WH = 12288;

    const float* csrc = (tid < 256) ? A : W;
    const int crow = (tid & 255) >> 1, ch = tid & 1;
    const int grow = ((tid < 256) ? m0 : n0) + crow;
    const uint32_t dhi = sb + ((tid < 256) ? AH : WH) + crow * 48 + ch * 16;
    const uint32_t dlo = dhi + 6144;
    const float* gsrc = csrc + (size_t)grow * E_ + ch * 8;

    const int lr = lane & 15, lkh = lane >> 4;
    uint32_t aAddr[2], wAddr[2];
    aAddr[0] = sb + AH + (wm * 32 +  0 + lr) * 48 + lkh * 16;
    aAddr[1] = sb + AH + (wm * 32 + 16 + lr) * 48 + lkh * 16;
    wAddr[0] = sb + WH + (wn * 32 +  0 + lr) * 48 + lkh * 16;
    wAddr[1] = sb + WH + (wn * 32 + 16 + lr) * 48 + lkh * 16;

    float acc[2][4][4] = {};

    float4 pv0 = *(const float4*)gsrc;
    float4 pv1 = *(const float4*)(gsrc + 4);
    cvt_store8(dhi, dlo, pv0, pv1);
    __syncthreads();

    for (int kb = 0; kb < 64; kb++) {
        if (kb < 63) {
            const float* g = gsrc + (kb + 1) * 16;
            pv0 = *(const float4*)g;
            pv1 = *(const float4*)(g + 4);
        }
        uint32_t aH[2][4], aL[2][4], wH[2][4], wL[2][4];
        ldsm4(aH[0], aAddr[0]);        ldsm4(aH[1], aAddr[1]);
        ldsm4(aL[0], aAddr[0] + 6144); ldsm4(aL[1], aAddr[1] + 6144);
        ldsm4(wH[0], wAddr[0]);        ldsm4(wH[1], wAddr[1]);
        ldsm4(wL[0], wAddr[0] + 6144); ldsm4(wL[1], wAddr[1] + 6144);
        #pragma unroll
        for (int i = 0; i < 2; i++)
            #pragma unroll
            for (int j = 0; j < 4; j++) {
                int jj = j >> 1, js = j & 1;
                uint32_t b0h = wH[jj][js], b1h = wH[jj][js + 2];
                uint32_t b0l = wL[jj][js], b1l = wL[jj][js + 2];
                mma_bf16(acc[i][j], aH[i], b0h, b1h);
                mma_bf16(acc[i][j], aH[i], b0l, b1l);
                mma_bf16(acc[i][j], aL[i], b0h, b1h);
            }
        __syncthreads();
        if (kb < 63) cvt_store8(dhi, dlo, pv0, pv1);
        __syncthreads();
    }

    #pragma unroll
    for (int i = 0; i < 2; i++) {
        int mrow = m0 + wm * 32 + i * 16 + (lane >> 2);
        #pragma unroll
        for (int j = 0; j < 4; j++) {
            int n = n0 + wn * 32 + j * 8 + (lane & 3) * 2;
            float bx = 0.f, by = 0.f;
            if (bias) { float2 bv = *(const float2*)&bias[n]; bx = bv.x; by = bv.y; }
            float2 v0 = {acc[i][j][0] * scale + bx, acc[i][j][1] * scale + by};
            float2 v1 = {acc[i][j][2] * scale + bx, acc[i][j][3] * scale + by};
            *(float2*)&C[(size_t)mrow * E_ + n]       = v0;
            *(float2*)&C[(size_t)(mrow + 8) * E_ + n] = v1;
        }
    }
}

__global__ __launch_bounds__(512) void proj3_mma(
    const float* __restrict__ q_in, const float* __restrict__ k_in,
    const float* __restrict__ v_in,
    const float* __restrict__ q_w, const float* __restrict__ k_w,
    const float* __restrict__ v_w,
    float* __restrict__ gq, float* __restrict__ gk, float* __restrict__ gv)
{
    if      (blockIdx.z == 0) gemm_mma_body(q_in, q_w, nullptr, gq, 0.125f);
    else if (blockIdx.z == 1) gemm_mma_body(k_in, k_w, nullptr, gk, 1.0f);
    else                      gemm_mma_body(v_in, v_w, nullptr, gv, 1.0f);
}

__global__ __launch_bounds__(512) void outproj_mma(
    const float* __restrict__ A, const float* __restrict__ W,
    const float* __restrict__ bias, float* __restrict__ C)
{
    gemm_mma_body(A, W, bias, C, 1.0f);
}

// ============ fused flash attention on mma.sync (bf16x3 QK, split-P PV) =====
// 256 thr / 8 warps; warp w owns q-rows 16w..16w+15; t-tile 64; dh 64.
// smem rows: 64 bf16 = 128 B, chunk swizzle c^(row&7).
__global__ __launch_bounds__(256, 2) void attn_fused_mma(
    const float* __restrict__ td,
    const float* __restrict__ fa, const float* __restrict__ fb,
    const float* __restrict__ fc, const float* __restrict__ fd)
{
    extern __shared__ __align__(16) unsigned char smem[];
    const uint32_t QH = 0, QL = 16384, KH = 32768, KL = 40960, VH = 49152, VL = 57344;
    float* tq_s = (float*)(smem + 65536);   // 128 floats
    float* tt_s = (float*)(smem + 66048);   // 64 floats
    const uint32_t sb = smem_u32(smem);

    const int q0 = blockIdx.x * 128, h = blockIdx.y, b = blockIdx.z;
    const int tid = threadIdx.x, lane = tid & 31, wid = tid >> 5;
    const float fav = *fa, fbv = *fb, fcv = *fc, fdv = *fd;

    // ---- convert Q tile to bf16 hi/lo smem (once) ----
    #pragma unroll
    for (int i = 0; i < 4; i++) {
        int gc = tid * 4 + i;                    // 1024 chunks: row=gc>>3, c=gc&7
        int row = gc >> 3, c = gc & 7;
        const float* g = g_Q + (size_t)b * E_ + (size_t)(q0 + row) * (B_ * E_) + h * DH_ + c * 8;
        float4 v0 = *(const float4*)g, v1 = *(const float4*)(g + 4);
        uint32_t off = (uint32_t)(row * 128 + ((c ^ (row & 7)) << 4));
        cvt_store8(sb + QH + off, sb + QL + off, v0, v1);
    }
    if (tid < 128) tq_s[tid] = td[b * S_ + q0 + tid];
    __syncthreads();

    const float tqa = tq_s[(wid << 4) + (lane >> 2)];
    const float tqb = tq_s[(wid << 4) + (lane >> 2) + 8];

    // lane-dependent ldsm tile decomposition
    const int t8 = lane >> 3, l7 = lane & 7;
    const int qrow  = (wid << 4) + ((t8 & 1) << 3) + l7;   // A: rows m, chunk-half t8>>1
    const int knrb  = ((t8 >> 1) << 3) + l7;               // K: rows n,  chunk-half t8&1
    const int vtrb  = ((t8 & 1) << 3) + l7;                // V: rows t,  chunk-half t8>>1

    float m0r = -1e30f, m1r = -1e30f, l0r = 0.f, l1r = 0.f;
    float o[8][4] = {};
    float* Sbase = g_S + ((size_t)(b * H_ + h) * S_) * S_;

    for (int t0 = 0; t0 < S_; t0 += 64) {
        // prefetch K/V fp32 (2 chunks each per thread)
        float4 kf[4], vf[4];
        #pragma unroll
        for (int i = 0; i < 2; i++) {
            int kc = tid * 2 + i, row = kc >> 3, c = kc & 7;
            const float* gk = g_K + (size_t)b * E_ + (size_t)(t0 + row) * (B_ * E_) + h * DH_ + c * 8;
            const float* gv = g_V + (size_t)b * E_ + (size_t)(t0 + row) * (B_ * E_) + h * DH_ + c * 8;
            kf[i*2] = *(const float4*)gk; kf[i*2+1] = *(const float4*)(gk + 4);
            vf[i*2] = *(const float4*)gv; vf[i*2+1] = *(const float4*)(gv + 4);
        }
        __syncthreads();   // previous iter's smem reads complete
        #pragma unroll
        for (int i = 0; i < 2; i++) {
            int kc = tid * 2 + i, row = kc >> 3, c = kc & 7;
            uint32_t off = (uint32_t)(row * 128 + ((c ^ (row & 7)) << 4));
            cvt_store8(sb + KH + off, sb + KL + off, kf[i*2], kf[i*2+1]);
            cvt_store8(sb + VH + off, sb + VL + off, vf[i*2], vf[i*2+1]);
        }
        if (tid < 64) tt_s[tid] = td[b * S_ + t0 + tid];
        __syncthreads();

        // ---- S = Q @ K^T (bf16x3) ----
        float s[8][4] = {};
        #pragma unroll
        for (int ks = 0; ks < 4; ks++) {
            int qc = 2 * ks + (t8 >> 1);
            uint32_t qa = sb + QH + qrow * 128 + ((qc ^ (qrow & 7)) << 4);
            uint32_t ah[4], al[4];
            ldsm4(ah, qa); ldsm4(al, qa + (QL - QH));
            #pragma unroll
            for (int np = 0; np < 4; np++) {
                int nrow = (np << 4) + knrb;
                int kc = 2 * ks + (t8 & 1);
                uint32_t ka = sb + KH + nrow * 128 + ((kc ^ (nrow & 7)) << 4);
                uint32_t bh[4], bl[4];
                ldsm4(bh, ka); ldsm4(bl, ka + (KL - KH));
                mma_bf16(s[2*np],   ah, bh[0], bh[1]);
                mma_bf16(s[2*np],   ah, bl[0], bl[1]);
                mma_bf16(s[2*np],   al, bh[0], bh[1]);
                mma_bf16(s[2*np+1], ah, bh[2], bh[3]);
                mma_bf16(s[2*np+1], ah, bl[2], bl[3]);
                mma_bf16(s[2*np+1], al, bh[2], bh[3]);
            }
        }

        // ---- forget factor, stash S, row max ----
        const int r0g = q0 + (wid << 4) + (lane >> 2);
        float mx0 = -1e30f, mx1 = -1e30f;
        #pragma unroll
        for (int j = 0; j < 8; j++) {
            float2 ttv = *(float2*)&tt_s[8 * j + 2 * (lane & 3)];
            float f00 = fcv * __fdividef(fbv, tqa - ttv.x + fav) + fdv;
            float f01 = fcv * __fdividef(fbv, tqa - ttv.y + fav) + fdv;
            float f10 = fcv * __fdividef(fbv, tqb - ttv.x + fav) + fdv;
            float f11 = fcv * __fdividef(fbv, tqb - ttv.y + fav) + fdv;
            s[j][0] *= f00; s[j][1] *= f01; s[j][2] *= f10; s[j][3] *= f11;
            int col = t0 + 8 * j + 2 * (lane & 3);
            *(float2*)&Sbase[(size_t)r0g * S_ + col]       = make_float2(s[j][0], s[j][1]);
            *(float2*)&Sbase[(size_t)(r0g + 8) * S_ + col] = make_float2(s[j][2], s[j][3]);
            mx0 = fmaxf(mx0, fmaxf(s[j][0], s[j][1]));
            mx1 = fmaxf(mx1, fmaxf(s[j][2], s[j][3]));
        }
        mx0 = fmaxf(mx0, __shfl_xor_sync(0xffffffffu, mx0, 1));
        mx0 = fmaxf(mx0, __shfl_xor_sync(0xffffffffu, mx0, 2));
        mx1 = fmaxf(mx1, __shfl_xor_sync(0xffffffffu, mx1, 1));
        mx1 = fmaxf(mx1, __shfl_xor_sync(0xffffffffu, mx1, 2));

        float mn0 = fmaxf(m0r, mx0), mn1 = fmaxf(m1r, mx1);
        float al0 = __expf(m0r - mn0), al1 = __expf(m1r - mn1);
        float ps0 = 0.f, ps1 = 0.f;
        #pragma unroll
        for (int j = 0; j < 8; j++) {
            s[j][0] = __expf(s[j][0] - mn0); s[j][1] = __expf(s[j][1] - mn0);
            s[j][2] = __expf(s[j][2] - mn1); s[j][3] = __expf(s[j][3] - mn1);
            ps0 += s[j][0] + s[j][1];
            ps1 += s[j][2] + s[j][3];
        }
        ps0 += __shfl_xor_sync(0xffffffffu, ps0, 1); ps0 += __shfl_xor_sync(0xffffffffu, ps0, 2);
        ps1 += __shfl_xor_sync(0xffffffffu, ps1, 1); ps1 += __shfl_xor_sync(0xffffffffu, ps1, 2);
        l0r = l0r * al0 + ps0; l1r = l1r * al1 + ps1;
        m0r = mn0; m1r = mn1;
        #pragma unroll
        for (int j = 0; j < 8; j++) {
            o[j][0] *= al0; o[j][1] *= al0; o[j][2] *= al1; o[j][3] *= al1;
        }

        // ---- O += P @ V (P hi/lo from C-frags, V hi/lo from smem) ----
        #pragma unroll
        for (int ks = 0; ks < 4; ks++) {
            uint32_t ah[4], alr[4];
            #pragma unroll
            for (int half = 0; half < 2; half++) {
                int jt = 2 * ks + half;
                uint32_t h0 = packbf2(s[jt][0], s[jt][1]);
                uint32_t h1 = packbf2(s[jt][2], s[jt][3]);
                float e00 = __uint_as_float(h0 << 16),      e01 = __uint_as_float(h0 & 0xFFFF0000u);
                float e10 = __uint_as_float(h1 << 16),      e11 = __uint_as_float(h1 & 0xFFFF0000u);
                ah [half*2]   = h0; ah [half*2+1] = h1;
                alr[half*2]   = packbf2(s[jt][0] - e00, s[jt][1] - e01);
                alr[half*2+1] = packbf2(s[jt][2] - e10, s[jt][3] - e11);
            }
            #pragma unroll
            for (int dp = 0; dp < 4; dp++) {
                int trow = (ks << 4) + vtrb;
                int dc = 2 * dp + (t8 >> 1);
                uint32_t va = sb + VH + trow * 128 + ((dc ^ (trow & 7)) << 4);
                uint32_t vh[4], vl[4];
                ldsm4t(vh, va); ldsm4t(vl, va + (VL - VH));
                mma_bf16(o[2*dp],   ah,  vh[0], vh[1]);
                mma_bf16(o[2*dp],   ah,  vl[0], vl[1]);
                mma_bf16(o[2*dp],   alr, vh[0], vh[1]);
                mma_bf16(o[2*dp+1], ah,  vh[2], vh[3]);
                mma_bf16(o[2*dp+1], ah,  vl[2], vl[3]);
                mma_bf16(o[2*dp+1], alr, vh[2], vh[3]);
            }
        }
    }

    // ---- epilogue ----
    float il0 = 1.0f / l0r, il1 = 1.0f / l1r;
    const int r0g = q0 + (wid << 4) + (lane >> 2);
    #pragma unroll
    for (int j = 0; j < 8; j++) {
        int d = h * DH_ + 8 * j + 2 * (lane & 3);
        *(float2*)&g_attn[((size_t)r0g * B_ + b) * E_ + d]       = make_float2(o[j][0] * il0, o[j][1] * il0);
        *(float2*)&g_attn[((size_t)(r0g + 8) * B_ + b) * E_ + d] = make_float2(o[j][2] * il1, o[j][3] * il1);
    }
    if ((lane & 3) == 0) {
        size_t base = (size_t)(b * H_ + h) * S_;
        g_m [base + r0g]     = m0r; g_il[base + r0g]     = il0;
        g_m [base + r0g + 8] = m1r; g_il[base + r0g + 8] = il1;
    }
}

// ====== avg_w[b,s,t] = (1/H) sum_h exp(S[b,h,s,t]-m)·il : streaming pass =====
__global__ __launch_bounds__(256) void attn_avg2(float* __restrict__ avgw)
{
    __shared__ float ms[H_], ils[H_];
    int s = blockIdx.x, b = blockIdx.y;
    int tid = threadIdx.x;
    if (tid < H_) {
        ms[tid]  = g_m [((size_t)b * H_ + tid) * S_ + s];
        ils[tid] = g_il[((size_t)b * H_ + tid) * S_ + s];
    }
    __syncthreads();

    float4 a0 = {0, 0, 0, 0}, a1 = {0, 0, 0, 0};
    #pragma unroll 4
    for (int h = 0; h < H_; h++) {
        const float4* row = (const float4*)&g_S[(((size_t)b * H_ + h) * S_ + s) * S_];
        float4 v0 = row[tid], v1 = row[tid + 256];
        float mh = ms[h], ih = ils[h];
        a0.x += __expf(v0.x - mh) * ih; a0.y += __expf(v0.y - mh) * ih;
        a0.z += __expf(v0.z - mh) * ih; a0.w += __expf(v0.w - mh) * ih;
        a1.x += __expf(v1.x - mh) * ih; a1.y += __expf(v1.y - mh) * ih;
        a1.z += __expf(v1.z - mh) * ih; a1.w += __expf(v1.w - mh) * ih;
    }
    const float invH = 1.0f / (float)H_;
    float4* out = (float4*)&avgw[((size_t)b * S_ + s) * S_];
    a0.x *= invH; a0.y *= invH; a0.z *= invH; a0.w *= invH;
    a1.x *= invH; a1.y *= invH; a1.z *= invH; a1.w *= invH;
    out[tid] = a0;
    out[tid + 256] = a1;
}

// ---------------------------------------------------------------------------
extern "C" void kernel_launch(void* const* d_in, const int* in_sizes, int n_in,
                              void* d_out, int out_size)
{
    const float* query = (const float*)d_in[0];
    const float* key_t = (const float*)d_in[1];
    const float* value = (const float*)d_in[2];
    const float* td    = (const float*)d_in[3];
    const float* q_w   = (const float*)d_in[4];
    const float* k_w   = (const float*)d_in[5];
    const float* v_w   = (const float*)d_in[6];
    const float* out_w = (const float*)d_in[7];
    const float* out_b = (const float*)d_in[8];
    const float* fa    = (const float*)d_in[9];
    const float* fb    = (const float*)d_in[10];
    const float* fc    = (const float*)d_in[11];
    const float* fd    = (const float*)d_in[12];

    float* Z    = (float*)d_out;                        // [S,B,E]
    float* avgw = (float*)d_out + (size_t)S_ * B_ * E_; // [B,S,S]

    float *gQ, *gK, *gV, *gA;
    cudaGetSymbolAddress((void**)&gQ, g_Q);
    cudaGetSymbolAddress((void**)&gK, g_K);
    cudaGetSymbolAddress((void**)&gV, g_V);
    cudaGetSymbolAddress((void**)&gA, g_attn);

    const int smem_attn = 66304;
    cudaFuncSetAttribute(attn_fused_mma, cudaFuncAttributeMaxDynamicSharedMemorySize, smem_attn);

    // Q,K,V projections (mma.sync bf16x3 tensor cores)
    proj3_mma<<<dim3(E_ / 128, MR_ / 128, 3), 512>>>(query, key_t, value,
                                                     q_w, k_w, v_w, gQ, gK, gV);
    // fused flash attention on tensor cores (writes g_attn, g_m, g_il, g_S)
    attn_fused_mma<<<dim3(S_ / 128, H_, B_), 256, smem_attn>>>(td, fa, fb, fc, fd);
    // output projection (mma.sync bf16x3)
    outproj_mma<<<dim3(E_ / 128, MR_ / 128), 512>>>(gA, out_w, out_b, Z);
    // head-averaged weights: stream stored scores
    attn_avg2<<<dim3(S_, B_), 256>>>(avgw);
}

// round 8
// speedup vs baseline: 7.2141x; 1.1182x over previous
#include <cuda_runtime.h>
#include <cuda_bf16.h>
#include <cstdint>

static constexpr int S_  = 2048;
static constexpr int B_  = 2;
static constexpr int E_  = 1024;
static constexpr int H_  = 16;
static constexpr int DH_ = 64;
static constexpr int MR_ = S_ * B_;   // 4096

// ---------------- scratch (device globals: no allocations allowed) ----------
__device__ float g_Q[MR_ * E_];
__device__ float g_K[MR_ * E_];
__device__ float g_V[MR_ * E_];
__device__ float g_attn[MR_ * E_];
__device__ float g_m [B_ * H_ * S_];
__device__ float g_il[B_ * H_ * S_];
__device__ float g_S[(size_t)B_ * H_ * S_ * S_];   // post-forget scores, 512 MB
// bf16 hi/lo operand pools (20M elems each): Q,K,V in (4M each), attn (4M),
// then qw,kw,vw,ow (1M each)
static constexpr size_t OFF_QI = 0, OFF_KI = 4u<<20, OFF_VI = 8u<<20, OFF_AT = 12u<<20;
static constexpr size_t OFF_QW = 16u<<20, OFF_KW = 17u<<20, OFF_VW = 18u<<20, OFF_OW = 19u<<20;
__device__ __nv_bfloat16 g_h[20u << 20];
__device__ __nv_bfloat16 g_l[20u << 20];

// ===================== mma.sync helpers (sm_80 baseline PTX) =================
__device__ __forceinline__ uint32_t smem_u32(const void* p) {
    uint32_t a;
    asm("{ .reg .u64 t; cvta.to.shared.u64 t, %1; cvt.u32.u64 %0, t; }" : "=r"(a) : "l"(p));
    return a;
}
__device__ __forceinline__ void ldsm4(uint32_t* r, uint32_t addr) {
    asm volatile("ldmatrix.sync.aligned.m8n8.x4.shared.b16 {%0,%1,%2,%3}, [%4];"
                 : "=r"(r[0]), "=r"(r[1]), "=r"(r[2]), "=r"(r[3]) : "r"(addr));
}
__device__ __forceinline__ void ldsm4t(uint32_t* r, uint32_t addr) {
    asm volatile("ldmatrix.sync.aligned.m8n8.x4.trans.shared.b16 {%0,%1,%2,%3}, [%4];"
                 : "=r"(r[0]), "=r"(r[1]), "=r"(r[2]), "=r"(r[3]) : "r"(addr));
}
__device__ __forceinline__ void mma_bf16(float* c, const uint32_t* a, uint32_t b0, uint32_t b1) {
    asm volatile("mma.sync.aligned.m16n8k16.row.col.f32.bf16.bf16.f32 "
                 "{%0,%1,%2,%3}, {%4,%5,%6,%7}, {%8,%9}, {%0,%1,%2,%3};"
                 : "+f"(c[0]), "+f"(c[1]), "+f"(c[2]), "+f"(c[3])
                 : "r"(a[0]), "r"(a[1]), "r"(a[2]), "r"(a[3]), "r"(b0), "r"(b1));
}
__device__ __forceinline__ uint32_t packbf2(float lo, float hi) {
    uint32_t r;
    asm("cvt.rn.bf16x2.f32 %0, %1, %2;" : "=r"(r) : "f"(hi), "f"(lo));
    return r;
}
__device__ __forceinline__ void cvt_store8(uint32_t dhi, uint32_t dlo, float4 v0, float4 v1) {
    float x[8] = {v0.x, v0.y, v0.z, v0.w, v1.x, v1.y, v1.z, v1.w};
    uint32_t hi[4], lo[4];
    #pragma unroll
    for (int p = 0; p < 4; p++) {
        uint32_t h = packbf2(x[2*p], x[2*p+1]);
        float xh = __uint_as_float(h << 16);
        float yh = __uint_as_float(h & 0xFFFF0000u);
        hi[p] = h;
        lo[p] = packbf2(x[2*p] - xh, x[2*p+1] - yh);
    }
    asm volatile("st.shared.v4.b32 [%0], {%1,%2,%3,%4};"
                 :: "r"(dhi), "r"(hi[0]), "r"(hi[1]), "r"(hi[2]), "r"(hi[3]) : "memory");
    asm volatile("st.shared.v4.b32 [%0], {%1,%2,%3,%4};"
                 :: "r"(dlo), "r"(lo[0]), "r"(lo[1]), "r"(lo[2]), "r"(lo[3]) : "memory");
}

// ============== split fp32 -> bf16 hi/lo pools (bandwidth-bound) =============
__global__ __launch_bounds__(256) void split_bf16(
    const float* __restrict__ src, __nv_bfloat16* __restrict__ hi,
    __nv_bfloat16* __restrict__ lo, int n8)
{
    int i = blockIdx.x * blockDim.x + threadIdx.x;
    if (i >= n8) return;
    float4 v0 = ((const float4*)src)[2*i], v1 = ((const float4*)src)[2*i+1];
    float x[8] = {v0.x, v0.y, v0.z, v0.w, v1.x, v1.y, v1.z, v1.w};
    uint4 h4, l4;
    uint32_t* hp = (uint32_t*)&h4; uint32_t* lp = (uint32_t*)&l4;
    #pragma unroll
    for (int p = 0; p < 4; p++) {
        uint32_t h = packbf2(x[2*p], x[2*p+1]);
        float xh = __uint_as_float(h << 16);
        float yh = __uint_as_float(h & 0xFFFF0000u);
        hp[p] = h;
        lp[p] = packbf2(x[2*p] - xh, x[2*p+1] - yh);
    }
    ((uint4*)hi)[i] = h4;
    ((uint4*)lo)[i] = l4;
}

// ===== bf16x3 GEMM, cp.async double-buffered: C = scale*(A @ W^T) + bias =====
// A/W pre-split bf16 hi/lo, K-major rows of 1024. Block 128x128, 256 thr.
// smem stage (40960 B): Ah[128x80B] Al Wh Wl; 2 stages.
__device__ __forceinline__ void gemm_cpasync_body(
    const __nv_bfloat16* __restrict__ Ah, const __nv_bfloat16* __restrict__ Al,
    const __nv_bfloat16* __restrict__ Wh, const __nv_bfloat16* __restrict__ Wl,
    const float* __restrict__ bias, float* __restrict__ C, float scale)
{
    extern __shared__ __align__(16) unsigned char sm[];
    const int tid = threadIdx.x, lane = tid & 31, wid = tid >> 5;
    const int wm = wid & 3, wn = wid >> 2;           // 4 m-tiles x 2 n-tiles
    const int m0 = blockIdx.y * 128, n0 = blockIdx.x * 128;
    const uint32_t sb = smem_u32(sm);

    // per-thread 8 cp.async chunks per stage
    uint32_t dofs[8]; const __nv_bfloat16* gsrc[8]; int grow_[8];
    #pragma unroll
    for (int c = 0; c < 8; c++) {
        int g = c * 256 + tid;
        int part = g >> 10, idx = g & 1023, hl = idx >> 9, rc = idx & 511;
        int row = rc >> 2, ch = rc & 3;
        const __nv_bfloat16* base = part ? (hl ? Wl : Wh) : (hl ? Al : Ah);
        grow_[c] = (part ? n0 : m0) + row;
        gsrc[c] = base + (size_t)grow_[c] * E_ + ch * 8;
        dofs[c] = (uint32_t)(part * 20480 + hl * 10240 + row * 80 + ch * 16);
    }

    #define ISSUE_STAGE(s, k0) do {                                            \
        uint32_t stb = sb + (s) * 40960;                                       \
        _Pragma("unroll")                                                      \
        for (int c = 0; c < 8; c++) {                                          \
            const void* gp = gsrc[c] + (k0);                                   \
            asm volatile("cp.async.ca.shared.global [%0], [%1], 16;"           \
                         :: "r"(stb + dofs[c]), "l"(gp) : "memory");           \
        }                                                                      \
        asm volatile("cp.async.commit_group;" ::: "memory");                   \
    } while (0)

    ISSUE_STAGE(0, 0);
    ISSUE_STAGE(1, 32);
    asm volatile("cp.async.wait_group 1;" ::: "memory");
    __syncthreads();

    float acc[2][8][4] = {};
    const int lr = lane & 15, lkh = lane >> 4;

    for (int kb = 0; kb < 32; kb++) {
        int s = kb & 1;
        uint32_t Ab = sb + s * 40960;
        uint32_t Wb = Ab + 20480;
        #pragma unroll
        for (int ks = 0; ks < 2; ks++) {
            uint32_t aH[2][4], aL[2][4];
            #pragma unroll
            for (int i = 0; i < 2; i++) {
                uint32_t ad = Ab + (wm * 32 + i * 16 + lr) * 80 + ks * 32 + lkh * 16;
                ldsm4(aH[i], ad); ldsm4(aL[i], ad + 10240);
            }
            #pragma unroll
            for (int np = 0; np < 4; np++) {
                uint32_t wa = Wb + (wn * 64 + np * 16 + lr) * 80 + ks * 32 + lkh * 16;
                uint32_t wHf[4], wLf[4];
                ldsm4(wHf, wa); ldsm4(wLf, wa + 10240);
                #pragma unroll
                for (int i = 0; i < 2; i++)
                    #pragma unroll
                    for (int js = 0; js < 2; js++) {
                        int j = np * 2 + js;
                        mma_bf16(acc[i][j], aH[i], wHf[js], wHf[js + 2]);
                        mma_bf16(acc[i][j], aH[i], wLf[js], wLf[js + 2]);
                        mma_bf16(acc[i][j], aL[i], wHf[js], wHf[js + 2]);
                    }
            }
        }
        __syncthreads();
        if (kb + 2 < 32) {
            ISSUE_STAGE(s, (kb + 2) * 32);
            asm volatile("cp.async.wait_group 1;" ::: "memory");
        } else {
            asm volatile("cp.async.wait_group 0;" ::: "memory");
        }
        __syncthreads();
    }
    #undef ISSUE_STAGE

    #pragma unroll
    for (int i = 0; i < 2; i++) {
        int mrow = m0 + wm * 32 + i * 16 + (lane >> 2);
        #pragma unroll
        for (int j = 0; j < 8; j++) {
            int n = n0 + wn * 64 + j * 8 + (lane & 3) * 2;
            float bx = 0.f, by = 0.f;
            if (bias) { float2 bv = *(const float2*)&bias[n]; bx = bv.x; by = bv.y; }
            float2 v0 = {acc[i][j][0] * scale + bx, acc[i][j][1] * scale + by};
            float2 v1 = {acc[i][j][2] * scale + bx, acc[i][j][3] * scale + by};
            *(float2*)&C[(size_t)mrow * E_ + n]       = v0;
            *(float2*)&C[(size_t)(mrow + 8) * E_ + n] = v1;
        }
    }
}

__global__ __launch_bounds__(256) void proj3_cp(
    float* __restrict__ gq, float* __restrict__ gk, float* __restrict__ gv)
{
    if (blockIdx.z == 0)
        gemm_cpasync_body(g_h + OFF_QI, g_l + OFF_QI, g_h + OFF_QW, g_l + OFF_QW,
                          nullptr, gq, 0.125f);
    else if (blockIdx.z == 1)
        gemm_cpasync_body(g_h + OFF_KI, g_l + OFF_KI, g_h + OFF_KW, g_l + OFF_KW,
                          nullptr, gk, 1.0f);
    else
        gemm_cpasync_body(g_h + OFF_VI, g_l + OFF_VI, g_h + OFF_VW, g_l + OFF_VW,
                          nullptr, gv, 1.0f);
}

__global__ __launch_bounds__(256) void outproj_cp(
    const float* __restrict__ bias, float* __restrict__ C)
{
    gemm_cpasync_body(g_h + OFF_AT, g_l + OFF_AT, g_h + OFF_OW, g_l + OFF_OW,
                      bias, C, 1.0f);
}

// ============ fused flash attention on mma.sync (bf16x3 QK, split-P PV) =====
__global__ __launch_bounds__(256, 2) void attn_fused_mma(
    const float* __restrict__ td,
    const float* __restrict__ fa, const float* __restrict__ fb,
    const float* __restrict__ fc, const float* __restrict__ fd)
{
    extern __shared__ __align__(16) unsigned char smem[];
    const uint32_t QH = 0, QL = 16384, KH = 32768, KL = 40960, VH = 49152, VL = 57344;
    float* tq_s = (float*)(smem + 65536);
    float* tt_s = (float*)(smem + 66048);
    const uint32_t sb = smem_u32(smem);

    const int q0 = blockIdx.x * 128, h = blockIdx.y, b = blockIdx.z;
    const int tid = threadIdx.x, lane = tid & 31, wid = tid >> 5;
    const float fav = *fa, fbv = *fb, fcv = *fc, fdv = *fd;

    #pragma unroll
    for (int i = 0; i < 4; i++) {
        int gc = tid * 4 + i;
        int row = gc >> 3, c = gc & 7;
        const float* g = g_Q + (size_t)b * E_ + (size_t)(q0 + row) * (B_ * E_) + h * DH_ + c * 8;
        float4 v0 = *(const float4*)g, v1 = *(const float4*)(g + 4);
        uint32_t off = (uint32_t)(row * 128 + ((c ^ (row & 7)) << 4));
        cvt_store8(sb + QH + off, sb + QL + off, v0, v1);
    }
    if (tid < 128) tq_s[tid] = td[b * S_ + q0 + tid];
    __syncthreads();

    const float tqa = tq_s[(wid << 4) + (lane >> 2)];
    const float tqb = tq_s[(wid << 4) + (lane >> 2) + 8];

    const int t8 = lane >> 3, l7 = lane & 7;
    const int qrow = (wid << 4) + ((t8 & 1) << 3) + l7;
    const int knrb = ((t8 >> 1) << 3) + l7;
    const int vtrb = ((t8 & 1) << 3) + l7;

    float m0r = -1e30f, m1r = -1e30f, l0r = 0.f, l1r = 0.f;
    float o[8][4] = {};
    float* Sbase = g_S + ((size_t)(b * H_ + h) * S_) * S_;

    for (int t0 = 0; t0 < S_; t0 += 64) {
        float4 kf[4], vf[4];
        #pragma unroll
        for (int i = 0; i < 2; i++) {
            int kc = tid * 2 + i, row = kc >> 3, c = kc & 7;
            const float* gk = g_K + (size_t)b * E_ + (size_t)(t0 + row) * (B_ * E_) + h * DH_ + c * 8;
            const float* gv = g_V + (size_t)b * E_ + (size_t)(t0 + row) * (B_ * E_) + h * DH_ + c * 8;
            kf[i*2] = *(const float4*)gk; kf[i*2+1] = *(const float4*)(gk + 4);
            vf[i*2] = *(const float4*)gv; vf[i*2+1] = *(const float4*)(gv + 4);
        }
        __syncthreads();
        #pragma unroll
        for (int i = 0; i < 2; i++) {
            int kc = tid * 2 + i, row = kc >> 3, c = kc & 7;
            uint32_t off = (uint32_t)(row * 128 + ((c ^ (row & 7)) << 4));
            cvt_store8(sb + KH + off, sb + KL + off, kf[i*2], kf[i*2+1]);
            cvt_store8(sb + VH + off, sb + VL + off, vf[i*2], vf[i*2+1]);
        }
        if (tid < 64) tt_s[tid] = td[b * S_ + t0 + tid];
        __syncthreads();

        float s[8][4] = {};
        #pragma unroll
        for (int ks = 0; ks < 4; ks++) {
            int qc = 2 * ks + (t8 >> 1);
            uint32_t qa = sb + QH + qrow * 128 + ((qc ^ (qrow & 7)) << 4);
            uint32_t ah[4], al[4];
            ldsm4(ah, qa); ldsm4(al, qa + (QL - QH));
            #pragma unroll
            for (int np = 0; np < 4; np++) {
                int nrow = (np << 4) + knrb;
                int kc = 2 * ks + (t8 & 1);
                uint32_t ka = sb + KH + nrow * 128 + ((kc ^ (nrow & 7)) << 4);
                uint32_t bh[4], bl[4];
                ldsm4(bh, ka); ldsm4(bl, ka + (KL - KH));
                mma_bf16(s[2*np],   ah, bh[0], bh[1]);
                mma_bf16(s[2*np],   ah, bl[0], bl[1]);
                mma_bf16(s[2*np],   al, bh[0], bh[1]);
                mma_bf16(s[2*np+1], ah, bh[2], bh[3]);
                mma_bf16(s[2*np+1], ah, bl[2], bl[3]);
                mma_bf16(s[2*np+1], al, bh[2], bh[3]);
            }
        }

        const int r0g = q0 + (wid << 4) + (lane >> 2);
        float mx0 = -1e30f, mx1 = -1e30f;
        #pragma unroll
        for (int j = 0; j < 8; j++) {
            float2 ttv = *(float2*)&tt_s[8 * j + 2 * (lane & 3)];
            float f00 = fcv * __fdividef(fbv, tqa - ttv.x + fav) + fdv;
            float f01 = fcv * __fdividef(fbv, tqa - ttv.y + fav) + fdv;
            float f10 = fcv * __fdividef(fbv, tqb - ttv.x + fav) + fdv;
            float f11 = fcv * __fdividef(fbv, tqb - ttv.y + fav) + fdv;
            s[j][0] *= f00; s[j][1] *= f01; s[j][2] *= f10; s[j][3] *= f11;
            int col = t0 + 8 * j + 2 * (lane & 3);
            *(float2*)&Sbase[(size_t)r0g * S_ + col]       = make_float2(s[j][0], s[j][1]);
            *(float2*)&Sbase[(size_t)(r0g + 8) * S_ + col] = make_float2(s[j][2], s[j][3]);
            mx0 = fmaxf(mx0, fmaxf(s[j][0], s[j][1]));
            mx1 = fmaxf(mx1, fmaxf(s[j][2], s[j][3]));
        }
        mx0 = fmaxf(mx0, __shfl_xor_sync(0xffffffffu, mx0, 1));
        mx0 = fmaxf(mx0, __shfl_xor_sync(0xffffffffu, mx0, 2));
        mx1 = fmaxf(mx1, __shfl_xor_sync(0xffffffffu, mx1, 1));
        mx1 = fmaxf(mx1, __shfl_xor_sync(0xffffffffu, mx1, 2));

        float mn0 = fmaxf(m0r, mx0), mn1 = fmaxf(m1r, mx1);
        float al0 = __expf(m0r - mn0), al1 = __expf(m1r - mn1);
        float ps0 = 0.f, ps1 = 0.f;
        #pragma unroll
        for (int j = 0; j < 8; j++) {
            s[j][0] = __expf(s[j][0] - mn0); s[j][1] = __expf(s[j][1] - mn0);
            s[j][2] = __expf(s[j][2] - mn1); s[j][3] = __expf(s[j][3] - mn1);
            ps0 += s[j][0] + s[j][1];
            ps1 += s[j][2] + s[j][3];
        }
        ps0 += __shfl_xor_sync(0xffffffffu, ps0, 1); ps0 += __shfl_xor_sync(0xffffffffu, ps0, 2);
        ps1 += __shfl_xor_sync(0xffffffffu, ps1, 1); ps1 += __shfl_xor_sync(0xffffffffu, ps1, 2);
        l0r = l0r * al0 + ps0; l1r = l1r * al1 + ps1;
        m0r = mn0; m1r = mn1;
        #pragma unroll
        for (int j = 0; j < 8; j++) {
            o[j][0] *= al0; o[j][1] *= al0; o[j][2] *= al1; o[j][3] *= al1;
        }

        #pragma unroll
        for (int ks = 0; ks < 4; ks++) {
            uint32_t ah[4], alr[4];
            #pragma unroll
            for (int half = 0; half < 2; half++) {
                int jt = 2 * ks + half;
                uint32_t h0 = packbf2(s[jt][0], s[jt][1]);
                uint32_t h1 = packbf2(s[jt][2], s[jt][3]);
                float e00 = __uint_as_float(h0 << 16), e01 = __uint_as_float(h0 & 0xFFFF0000u);
                float e10 = __uint_as_float(h1 << 16), e11 = __uint_as_float(h1 & 0xFFFF0000u);
                ah [half*2]   = h0; ah [half*2+1] = h1;
                alr[half*2]   = packbf2(s[jt][0] - e00, s[jt][1] - e01);
                alr[half*2+1] = packbf2(s[jt][2] - e10, s[jt][3] - e11);
            }
            #pragma unroll
            for (int dp = 0; dp < 4; dp++) {
                int trow = (ks << 4) + vtrb;
                int dc = 2 * dp + (t8 >> 1);
                uint32_t va = sb + VH + trow * 128 + ((dc ^ (trow & 7)) << 4);
                uint32_t vh[4], vl[4];
                ldsm4t(vh, va); ldsm4t(vl, va + (VL - VH));
                mma_bf16(o[2*dp],   ah,  vh[0], vh[1]);
                mma_bf16(o[2*dp],   ah,  vl[0], vl[1]);
                mma_bf16(o[2*dp],   alr, vh[0], vh[1]);
                mma_bf16(o[2*dp+1], ah,  vh[2], vh[3]);
                mma_bf16(o[2*dp+1], ah,  vl[2], vl[3]);
                mma_bf16(o[2*dp+1], alr, vh[2], vh[3]);
            }
        }
    }

    float il0 = 1.0f / l0r, il1 = 1.0f / l1r;
    const int r0g = q0 + (wid << 4) + (lane >> 2);
    #pragma unroll
    for (int j = 0; j < 8; j++) {
        int d = h * DH_ + 8 * j + 2 * (lane & 3);
        *(float2*)&g_attn[((size_t)r0g * B_ + b) * E_ + d]       = make_float2(o[j][0] * il0, o[j][1] * il0);
        *(float2*)&g_attn[((size_t)(r0g + 8) * B_ + b) * E_ + d] = make_float2(o[j][2] * il1, o[j][3] * il1);
    }
    if ((lane & 3) == 0) {
        size_t base = (size_t)(b * H_ + h) * S_;
        g_m [base + r0g]     = m0r; g_il[base + r0g]     = il0;
        g_m [base + r0g + 8] = m1r; g_il[base + r0g + 8] = il1;
    }
}

// ====== avg_w[b,s,t] = (1/H) sum_h exp(S[b,h,s,t]-m)·il : streaming pass =====
__global__ __launch_bounds__(256) void attn_avg2(float* __restrict__ avgw)
{
    __shared__ float ms[H_], ils[H_];
    int s = blockIdx.x, b = blockIdx.y;
    int tid = threadIdx.x;
    if (tid < H_) {
        ms[tid]  = g_m [((size_t)b * H_ + tid) * S_ + s];
        ils[tid] = g_il[((size_t)b * H_ + tid) * S_ + s];
    }
    __syncthreads();

    float4 a0 = {0, 0, 0, 0}, a1 = {0, 0, 0, 0};
    #pragma unroll 4
    for (int h = 0; h < H_; h++) {
        const float4* row = (const float4*)&g_S[(((size_t)b * H_ + h) * S_ + s) * S_];
        float4 v0 = row[tid], v1 = row[tid + 256];
        float mh = ms[h], ih = ils[h];
        a0.x += __expf(v0.x - mh) * ih; a0.y += __expf(v0.y - mh) * ih;
        a0.z += __expf(v0.z - mh) * ih; a0.w += __expf(v0.w - mh) * ih;
        a1.x += __expf(v1.x - mh) * ih; a1.y += __expf(v1.y - mh) * ih;
        a1.z += __expf(v1.z - mh) * ih; a1.w += __expf(v1.w - mh) * ih;
    }
    const float invH = 1.0f / (float)H_;
    float4* out = (float4*)&avgw[((size_t)b * S_ + s) * S_];
    a0.x *= invH; a0.y *= invH; a0.z *= invH; a0.w *= invH;
    a1.x *= invH; a1.y *= invH; a1.z *= invH; a1.w *= invH;
    out[tid] = a0;
    out[tid + 256] = a1;
}

// ---------------------------------------------------------------------------
extern "C" void kernel_launch(void* const* d_in, const int* in_sizes, int n_in,
                              void* d_out, int out_size)
{
    const float* query = (const float*)d_in[0];
    const float* key_t = (const float*)d_in[1];
    const float* value = (const float*)d_in[2];
    const float* td    = (const float*)d_in[3];
    const float* q_w   = (const float*)d_in[4];
    const float* k_w   = (const float*)d_in[5];
    const float* v_w   = (const float*)d_in[6];
    const float* out_w = (const float*)d_in[7];
    const float* out_b = (const float*)d_in[8];
    const float* fa    = (const float*)d_in[9];
    const float* fb    = (const float*)d_in[10];
    const float* fc    = (const float*)d_in[11];
    const float* fd    = (const float*)d_in[12];

    float* Z    = (float*)d_out;                        // [S,B,E]
    float* avgw = (float*)d_out + (size_t)S_ * B_ * E_; // [B,S,S]

    float *gQ, *gK, *gV, *gA;
    __nv_bfloat16 *gh, *gl;
    cudaGetSymbolAddress((void**)&gQ, g_Q);
    cudaGetSymbolAddress((void**)&gK, g_K);
    cudaGetSymbolAddress((void**)&gV, g_V);
    cudaGetSymbolAddress((void**)&gA, g_attn);
    cudaGetSymbolAddress((void**)&gh, g_h);
    cudaGetSymbolAddress((void**)&gl, g_l);

    const int smem_attn = 66304;
    const int smem_gemm = 81920;
    cudaFuncSetAttribute(attn_fused_mma, cudaFuncAttributeMaxDynamicSharedMemorySize, smem_attn);
    cudaFuncSetAttribute(proj3_cp,   cudaFuncAttributeMaxDynamicSharedMemorySize, smem_gemm);
    cudaFuncSetAttribute(outproj_cp, cudaFuncAttributeMaxDynamicSharedMemorySize, smem_gemm);

    const int n8_in = MR_ * E_ / 8;     // 524288
    const int n8_w  = E_ * E_ / 8;      // 131072
    // split inputs + weights into bf16 hi/lo pools
    split_bf16<<<n8_in / 256, 256>>>(query, gh + OFF_QI, gl + OFF_QI, n8_in);
    split_bf16<<<n8_in / 256, 256>>>(key_t, gh + OFF_KI, gl + OFF_KI, n8_in);
    split_bf16<<<n8_in / 256, 256>>>(value, gh + OFF_VI, gl + OFF_VI, n8_in);
    split_bf16<<<n8_w  / 256, 256>>>(q_w,   gh + OFF_QW, gl + OFF_QW, n8_w);
    split_bf16<<<n8_w  / 256, 256>>>(k_w,   gh + OFF_KW, gl + OFF_KW, n8_w);
    split_bf16<<<n8_w  / 256, 256>>>(v_w,   gh + OFF_VW, gl + OFF_VW, n8_w);
    split_bf16<<<n8_w  / 256, 256>>>(out_w, gh + OFF_OW, gl + OFF_OW, n8_w);
    // Q,K,V projections (cp.async bf16x3 tensor cores)
    proj3_cp<<<dim3(E_ / 128, MR_ / 128, 3), 256, smem_gemm>>>(gQ, gK, gV);
    // fused flash attention on tensor cores (writes g_attn, g_m, g_il, g_S)
    attn_fused_mma<<<dim3(S_ / 128, H_, B_), 256, smem_attn>>>(td, fa, fb, fc, fd);
    // split attention output, then output projection
    split_bf16<<<n8_in / 256, 256>>>(gA, gh + OFF_AT, gl + OFF_AT, n8_in);
    outproj_cp<<<dim3(E_ / 128, MR_ / 128), 256, smem_gemm>>>(out_b, Z);
    // head-averaged weights: stream stored scores
    attn_avg2<<<dim3(S_, B_), 256>>>(avgw);
}